// round 1
// baseline (speedup 1.0000x reference)
#include <cuda_runtime.h>
#include <cstdint>
#include <math.h>

// ---------------------------------------------------------------------------
// Scratch (static __device__ arrays; no allocation allowed)
// ---------------------------------------------------------------------------
#define NPIX 65536
__device__ float g_grid[NPIX * 32];            // 8 MB
__device__ float g_mid [NPIX * 1024];          // 256 MB
__device__ float g_h2  [NPIX * 512];           // 128 MB
__device__ float g_wm1F[8 * 512 * 512];        // 8 MB
__device__ float g_wm1G[8 * 512 * 512];        // 8 MB
__device__ float g_wm2F[8 * 256 * 256];        // 2 MB
__device__ float g_wm2G[8 * 256 * 256];        // 2 MB
__device__ float g_conv0[768 * 8 * 8];
__device__ float g_conv1[768 * 8 * 8];
__device__ float g_feat[2048];
__device__ float g_bias1[1024];

// ---------------------------------------------------------------------------
// Grid features: IMG_GRID[n, c], n = i*256 + j
//   c even -> base = r[i], c odd -> base = r[j],  r[t] = (t-128)*pi/256
//   scale_c = 2^((c/2)/2);  value = sin(base * scale)
// ---------------------------------------------------------------------------
__global__ void grid_kernel(float* __restrict__ g) {
    int idx = blockIdx.x * blockDim.x + threadIdx.x;      // n*32 + c
    int n = idx >> 5, c = idx & 31;
    int i = n >> 8, j = n & 255;
    float r = (float)(((c & 1) ? j : i) - 128) * (float)(3.14159265358979323846 / 256.0);
    float s = exp2f(0.5f * (float)(c >> 1));
    g[idx] = sinf(r * s);
}

// ---------------------------------------------------------------------------
// Naive grouped 3x3 conv + leaky_relu.  One block per output channel.
// ---------------------------------------------------------------------------
__global__ void conv3x3_kernel(const float* __restrict__ in, const float* __restrict__ w,
                               const float* __restrict__ bias, float* __restrict__ out,
                               int Cin, int Cout, int Hin, int Win,
                               int Hout, int Wout, int pad, int groups) {
    int oc = blockIdx.x;
    int icpg = Cin / groups;
    int ocpg = Cout / groups;
    int grp = oc / ocpg;
    extern __shared__ float sw[];                       // icpg * 9 weights
    for (int i = threadIdx.x; i < icpg * 9; i += blockDim.x)
        sw[i] = w[(size_t)oc * icpg * 9 + i];
    __syncthreads();

    int tid = threadIdx.x;
    if (tid < Hout * Wout) {
        int oy = tid / Wout, ox = tid % Wout;
        float acc = bias[oc];
        const float* inb = in + (size_t)grp * icpg * Hin * Win;
        for (int ic = 0; ic < icpg; ic++) {
            const float* ip = inb + (size_t)ic * Hin * Win;
            const float* wp = sw + ic * 9;
            #pragma unroll
            for (int ky = 0; ky < 3; ky++) {
                int iy = oy + ky - pad;
                if (iy < 0 || iy >= Hin) continue;
                #pragma unroll
                for (int kx = 0; kx < 3; kx++) {
                    int ix = ox + kx - pad;
                    if (ix < 0 || ix >= Win) continue;
                    acc = fmaf(ip[iy * Win + ix], wp[ky * 3 + kx], acc);
                }
            }
        }
        out[(size_t)oc * Hout * Wout + tid] = acc > 0.f ? acc : 0.01f * acc;
    }
}

// ---------------------------------------------------------------------------
// Weight-norm:  w[o,:] = v[o,:] * g[o] / ||v[o,:]||    (rows of all 8 mats)
// ---------------------------------------------------------------------------
__global__ void wnorm_kernel(const float* __restrict__ v, const float* __restrict__ g,
                             float* __restrict__ w, int K) {
    int row = blockIdx.x;
    const float* vr = v + (size_t)row * K;
    float s = 0.f;
    for (int k = threadIdx.x; k < K; k += blockDim.x) { float x = vr[k]; s = fmaf(x, x, s); }
    __shared__ float red[128];
    red[threadIdx.x] = s;
    __syncthreads();
    for (int o = 64; o; o >>= 1) {
        if (threadIdx.x < o) red[threadIdx.x] += red[threadIdx.x + o];
        __syncthreads();
    }
    float scale = g[row] / sqrtf(red[0]);
    for (int k = threadIdx.x; k < K; k += blockDim.x)
        w[(size_t)row * K + k] = vr[k] * scale;
}

// ---------------------------------------------------------------------------
// bias1[j] = b1[j] + sum_k feat[k] * w1[j, 32+k]   (one warp per j)
// ---------------------------------------------------------------------------
__global__ void bias1_kernel(const float* __restrict__ feat, const float* __restrict__ w1,
                             const float* __restrict__ b1, float* __restrict__ out) {
    int j = blockIdx.x * 8 + (threadIdx.x >> 5);
    int lane = threadIdx.x & 31;
    const float* wr = w1 + (size_t)j * 2080 + 32;
    float s = 0.f;
    for (int k = lane; k < 2048; k += 32) s = fmaf(feat[k], wr[k], s);
    #pragma unroll
    for (int o = 16; o; o >>= 1) s += __shfl_down_sync(0xffffffffu, s, o);
    if (lane == 0) out[j] = b1[j] + s;
}

// ---------------------------------------------------------------------------
// Generic fp32 SGEMM, 128x128x16 tile, 8x8 per thread, 256 threads.
// C[m,n] = sum_k A[m,k] * B[n,k]     (B row-major [N,K], stride ldb)
// Requires M%128==0, N%128==0, K%16==0, lda/ldb/ldc%4==0.
// ---------------------------------------------------------------------------
enum { EP_BIAS = 0, EP_LRELU_BIAS = 1, EP_ADD_INSIDE = 2, EP_RES_OUT = 3 };

#define BM 128
#define BN 128
#define BKK 16
#define TM 8
#define TN 8

template <int EP>
__global__ __launch_bounds__(256, 2)
void sgemm_kernel(const float* __restrict__ A, int lda,
                  const float* __restrict__ B, int ldb,
                  float* __restrict__ C, int ldc,
                  const float* __restrict__ Res, int ldres,
                  const float* __restrict__ bias,
                  int K) {
    __shared__ float As[BKK][BM + 4];
    __shared__ float Bs[BKK][BN + 4];

    int tid  = threadIdx.x;
    long brow = blockIdx.y;
    long bcol = blockIdx.x;

    A += brow * BM * (long)lda;
    B += bcol * BN * (long)ldb;
    C += brow * BM * (long)ldc + bcol * BN;
    Res += brow * BM * (long)ldres + bcol * BN;
    const float* biasp = bias + bcol * BN;

    int lrow = tid >> 2;            // 0..63
    int lcol = (tid & 3) * 4;       // 0,4,8,12

    float acc[TM][TN] = {};
    int tr = (tid >> 4) * TM;
    int tc = (tid & 15) * TN;

    for (int k0 = 0; k0 < K; k0 += BKK) {
        #pragma unroll
        for (int h = 0; h < 2; h++) {
            int r = lrow + 64 * h;
            float4 va = *reinterpret_cast<const float4*>(A + (long)r * lda + k0 + lcol);
            As[lcol + 0][r] = va.x;
            As[lcol + 1][r] = va.y;
            As[lcol + 2][r] = va.z;
            As[lcol + 3][r] = va.w;
            float4 vb = *reinterpret_cast<const float4*>(B + (long)r * ldb + k0 + lcol);
            Bs[lcol + 0][r] = vb.x;
            Bs[lcol + 1][r] = vb.y;
            Bs[lcol + 2][r] = vb.z;
            Bs[lcol + 3][r] = vb.w;
        }
        __syncthreads();

        #pragma unroll
        for (int k = 0; k < BKK; k++) {
            float4 a0 = *reinterpret_cast<const float4*>(&As[k][tr]);
            float4 a1 = *reinterpret_cast<const float4*>(&As[k][tr + 4]);
            float4 b0 = *reinterpret_cast<const float4*>(&Bs[k][tc]);
            float4 b1 = *reinterpret_cast<const float4*>(&Bs[k][tc + 4]);
            float ra[TM] = {a0.x, a0.y, a0.z, a0.w, a1.x, a1.y, a1.z, a1.w};
            float rb[TN] = {b0.x, b0.y, b0.z, b0.w, b1.x, b1.y, b1.z, b1.w};
            #pragma unroll
            for (int i = 0; i < TM; i++)
                #pragma unroll
                for (int j = 0; j < TN; j++)
                    acc[i][j] = fmaf(ra[i], rb[j], acc[i][j]);
        }
        __syncthreads();
    }

    #pragma unroll
    for (int i = 0; i < TM; i++) {
        long row = tr + i;
        #pragma unroll
        for (int j = 0; j < TN; j++) {
            int col = tc + j;
            float v = acc[i][j];
            if (EP == EP_BIAS) {
                v += biasp[col];
            } else if (EP == EP_LRELU_BIAS) {
                v += biasp[col];
                v = v > 0.f ? v : 0.01f * v;
            } else if (EP == EP_ADD_INSIDE) {
                v += Res[row * ldres + col];
                v = v > 0.f ? v : 0.01f * v;
            } else {  // EP_RES_OUT
                v += biasp[col];
                v = v > 0.f ? v : 0.01f * v;
                v += Res[row * ldres + col];
            }
            C[row * ldc + col] = v;
        }
    }
}

static void launch_gemm(int ep, const float* A, int lda, const float* B, int ldb,
                        float* C, int ldc, const float* Res, int ldres,
                        const float* bias, int M, int N, int K) {
    dim3 grd(N / BN, M / BM);
    switch (ep) {
        case EP_BIAS:       sgemm_kernel<EP_BIAS>      <<<grd, 256>>>(A, lda, B, ldb, C, ldc, Res, ldres, bias, K); break;
        case EP_LRELU_BIAS: sgemm_kernel<EP_LRELU_BIAS><<<grd, 256>>>(A, lda, B, ldb, C, ldc, Res, ldres, bias, K); break;
        case EP_ADD_INSIDE: sgemm_kernel<EP_ADD_INSIDE><<<grd, 256>>>(A, lda, B, ldb, C, ldc, Res, ldres, bias, K); break;
        default:            sgemm_kernel<EP_RES_OUT>   <<<grd, 256>>>(A, lda, B, ldb, C, ldc, Res, ldres, bias, K); break;
    }
}

// ---------------------------------------------------------------------------
// Head: rgb = sigmoid(h2 @ w3.T + b3) * 1.1 - 0.05, transposed to [3,65536]
// One warp per pixel.
// ---------------------------------------------------------------------------
__global__ void head_kernel(const float* __restrict__ h2, const float* __restrict__ w3,
                            const float* __restrict__ b3, float* __restrict__ out) {
    __shared__ float sw[1536];
    for (int i = threadIdx.x; i < 1536; i += blockDim.x) sw[i] = w3[i];
    __syncthreads();
    int n = (blockIdx.x * blockDim.x + threadIdx.x) >> 5;
    int lane = threadIdx.x & 31;
    const float* hr = h2 + (size_t)n * 512;
    float d0 = 0.f, d1 = 0.f, d2 = 0.f;
    for (int t = lane; t < 512; t += 32) {
        float x = hr[t];
        d0 = fmaf(x, sw[t], d0);
        d1 = fmaf(x, sw[512 + t], d1);
        d2 = fmaf(x, sw[1024 + t], d2);
    }
    #pragma unroll
    for (int o = 16; o; o >>= 1) {
        d0 += __shfl_down_sync(0xffffffffu, d0, o);
        d1 += __shfl_down_sync(0xffffffffu, d1, o);
        d2 += __shfl_down_sync(0xffffffffu, d2, o);
    }
    if (lane == 0) {
        out[n]          = 1.1f / (1.f + expf(-(d0 + b3[0]))) - 0.05f;
        out[65536 + n]  = 1.1f / (1.f + expf(-(d1 + b3[1]))) - 0.05f;
        out[131072 + n] = 1.1f / (1.f + expf(-(d2 + b3[2]))) - 0.05f;
    }
}

// ---------------------------------------------------------------------------
// kernel_launch
// ---------------------------------------------------------------------------
extern "C" void kernel_launch(void* const* d_in, const int* in_sizes, int n_in,
                              void* d_out, int out_size) {
    const float* feature = (const float*)d_in[0];
    const float* cw1 = (const float*)d_in[1];  const float* cb1 = (const float*)d_in[2];
    const float* cw2 = (const float*)d_in[3];  const float* cb2 = (const float*)d_in[4];
    const float* cw3 = (const float*)d_in[5];  const float* cb3 = (const float*)d_in[6];
    const float* cw4 = (const float*)d_in[7];  const float* cb4 = (const float*)d_in[8];
    const float* cw5 = (const float*)d_in[9];  const float* cb5 = (const float*)d_in[10];
    const float* w1  = (const float*)d_in[11]; const float* b1  = (const float*)d_in[12];
    const float* m1_vf = (const float*)d_in[13]; const float* m1_gf = (const float*)d_in[14];
    const float* m1_bf = (const float*)d_in[15]; const float* m1_vg = (const float*)d_in[16];
    const float* m1_gg = (const float*)d_in[17]; const float* m1_bg = (const float*)d_in[18];
    const float* w2  = (const float*)d_in[19]; const float* b2  = (const float*)d_in[20];
    const float* m2_vf = (const float*)d_in[21]; const float* m2_gf = (const float*)d_in[22];
    const float* m2_bf = (const float*)d_in[23]; const float* m2_vg = (const float*)d_in[24];
    const float* m2_gg = (const float*)d_in[25]; const float* m2_bg = (const float*)d_in[26];
    const float* w3  = (const float*)d_in[27]; const float* b3  = (const float*)d_in[28];
    float* out = (float*)d_out;

    float *grid_, *mid, *h2, *wm1F, *wm1G, *wm2F, *wm2G, *conv0, *conv1, *feat, *bias1;
    cudaGetSymbolAddress((void**)&grid_, g_grid);
    cudaGetSymbolAddress((void**)&mid,   g_mid);
    cudaGetSymbolAddress((void**)&h2,    g_h2);
    cudaGetSymbolAddress((void**)&wm1F,  g_wm1F);
    cudaGetSymbolAddress((void**)&wm1G,  g_wm1G);
    cudaGetSymbolAddress((void**)&wm2F,  g_wm2F);
    cudaGetSymbolAddress((void**)&wm2G,  g_wm2G);
    cudaGetSymbolAddress((void**)&conv0, g_conv0);
    cudaGetSymbolAddress((void**)&conv1, g_conv1);
    cudaGetSymbolAddress((void**)&feat,  g_feat);
    cudaGetSymbolAddress((void**)&bias1, g_bias1);

    // --- positional grid features ---
    grid_kernel<<<(NPIX * 32) / 256, 256>>>(grid_);

    // --- conv stack ---
    conv3x3_kernel<<<768, 64, 448 * 9 * 4>>>(feature, cw1, cb1, conv0, 1792, 768, 8, 8, 8, 8, 1, 4);
    conv3x3_kernel<<<768, 64, 256 * 9 * 4>>>(conv0, cw2, cb2, conv1, 768, 768, 8, 8, 8, 8, 1, 3);
    conv3x3_kernel<<<768, 64, 384 * 9 * 4>>>(conv1, cw3, cb3, conv0, 768, 768, 8, 8, 8, 8, 1, 2);
    conv3x3_kernel<<<768, 64, 256 * 9 * 4>>>(conv0, cw4, cb4, conv1, 768, 768, 8, 8, 6, 6, 0, 3);
    conv3x3_kernel<<<128, 64, 768 * 9 * 4>>>(conv1, cw5, cb5, feat, 768, 128, 6, 6, 4, 4, 0, 1);

    // --- fold feat @ w1[:,32:].T + b1 into a bias vector ---
    bias1_kernel<<<128, 256>>>(feat, w1, b1, bias1);

    // --- weight-norm preprocessing ---
    wnorm_kernel<<<8 * 512, 128>>>(m1_vf, m1_gf, wm1F, 512);
    wnorm_kernel<<<8 * 512, 128>>>(m1_vg, m1_gg, wm1G, 512);
    wnorm_kernel<<<8 * 256, 128>>>(m2_vf, m2_gf, wm2F, 256);
    wnorm_kernel<<<8 * 256, 128>>>(m2_vg, m2_gg, wm2G, 256);

    // --- mid = lrelu(grid @ w1[:, :32].T + bias1)   [65536, 1024] ---
    launch_gemm(EP_LRELU_BIAS, grid_, 32, w1, 2080, mid, 1024,
                mid, 1024, bias1, NPIX, 1024, 32);

    // --- mem stack 1: halves of 1024 (512 each) ---
    for (int s = 0; s < 8; s++) {
        launch_gemm(EP_RES_OUT, mid + 512, 1024, wm1F + (size_t)s * 512 * 512, 512,
                    mid, 1024, mid, 1024, m1_bf + s * 512, NPIX, 512, 512);
        launch_gemm(EP_RES_OUT, mid, 1024, wm1G + (size_t)s * 512 * 512, 512,
                    mid + 512, 1024, mid + 512, 1024, m1_bg + s * 512, NPIX, 512, 512);
    }

    // --- h2 = lrelu(grid @ w2[:, :32].T + b2 + mid @ w2[:, 32:].T) ---
    launch_gemm(EP_BIAS, grid_, 32, w2, 1056, h2, 512, h2, 512, b2, NPIX, 512, 32);
    launch_gemm(EP_ADD_INSIDE, mid, 1024, w2 + 32, 1056, h2, 512, h2, 512, b2, NPIX, 512, 1024);

    // --- mem stack 2: halves of 512 (256 each) ---
    for (int s = 0; s < 8; s++) {
        launch_gemm(EP_RES_OUT, h2 + 256, 512, wm2F + (size_t)s * 256 * 256, 256,
                    h2, 512, h2, 512, m2_bf + s * 256, NPIX, 256, 256);
        launch_gemm(EP_RES_OUT, h2, 512, wm2G + (size_t)s * 256 * 256, 256,
                    h2 + 256, 512, h2 + 256, 512, m2_bg + s * 256, NPIX, 256, 256);
    }

    // --- head ---
    head_kernel<<<NPIX / 8, 256>>>(h2, w3, b3, out);
}

// round 2
// speedup vs baseline: 2.9134x; 2.9134x over previous
#include <cuda_runtime.h>
#include <cstdint>
#include <math.h>

// ---------------------------------------------------------------------------
// Scratch (static __device__ arrays; no allocation allowed)
// ---------------------------------------------------------------------------
#define NPIX 65536
__device__ float g_grid[NPIX * 32];
__device__ float g_mid [NPIX * 1024];
__device__ float g_h2  [NPIX * 512];
__device__ float g_wm1F[8 * 512 * 512];
__device__ float g_wm1G[8 * 512 * 512];
__device__ float g_wm2F[8 * 256 * 256];
__device__ float g_wm2G[8 * 256 * 256];
__device__ float g_conv0[768 * 8 * 8];
__device__ float g_conv1[768 * 8 * 8];
__device__ float g_feat[2048];
__device__ float g_bias1[1024];

// ---------------------------------------------------------------------------
// Grid features
// ---------------------------------------------------------------------------
__global__ void grid_kernel(float* __restrict__ g) {
    int idx = blockIdx.x * blockDim.x + threadIdx.x;      // n*32 + c
    int n = idx >> 5, c = idx & 31;
    int i = n >> 8, j = n & 255;
    float r = (float)(((c & 1) ? j : i) - 128) * (float)(3.14159265358979323846 / 256.0);
    float s = exp2f(0.5f * (float)(c >> 1));
    g[idx] = sinf(r * s);
}

// ---------------------------------------------------------------------------
// Grouped 3x3 conv + leaky_relu. One block per output channel, 256 threads:
// 4-way split over input channels, smem reduction.
// ---------------------------------------------------------------------------
__global__ void conv3x3_kernel(const float* __restrict__ in, const float* __restrict__ w,
                               const float* __restrict__ bias, float* __restrict__ out,
                               int Cin, int Cout, int Hin, int Win,
                               int Hout, int Wout, int pad, int groups) {
    int oc = blockIdx.x;
    int icpg = Cin / groups;
    int ocpg = Cout / groups;
    int grp = oc / ocpg;
    extern __shared__ float sm[];
    float* sw  = sm;               // icpg*9
    float* red = sm + icpg * 9;    // 4*64
    for (int i = threadIdx.x; i < icpg * 9; i += blockDim.x)
        sw[i] = w[(size_t)oc * icpg * 9 + i];
    __syncthreads();

    int icq = threadIdx.x >> 6;        // 0..3
    int px  = threadIdx.x & 63;
    float acc = 0.f;
    if (px < Hout * Wout) {
        int oy = px / Wout, ox = px % Wout;
        const float* inb = in + (size_t)grp * icpg * Hin * Win;
        for (int ic = icq; ic < icpg; ic += 4) {
            const float* ip = inb + (size_t)ic * Hin * Win;
            const float* wp = sw + ic * 9;
            #pragma unroll
            for (int ky = 0; ky < 3; ky++) {
                int iy = oy + ky - pad;
                if (iy < 0 || iy >= Hin) continue;
                #pragma unroll
                for (int kx = 0; kx < 3; kx++) {
                    int ix = ox + kx - pad;
                    if (ix < 0 || ix >= Win) continue;
                    acc = fmaf(ip[iy * Win + ix], wp[ky * 3 + kx], acc);
                }
            }
        }
    }
    red[icq * 64 + px] = acc;
    __syncthreads();
    if (icq == 0 && px < Hout * Wout) {
        float v = bias[oc] + red[px] + red[64 + px] + red[128 + px] + red[192 + px];
        out[(size_t)oc * Hout * Wout + px] = v > 0.f ? v : 0.01f * v;
    }
}

// ---------------------------------------------------------------------------
// Weight-norm
// ---------------------------------------------------------------------------
__global__ void wnorm_kernel(const float* __restrict__ v, const float* __restrict__ g,
                             float* __restrict__ w, int K) {
    int row = blockIdx.x;
    const float* vr = v + (size_t)row * K;
    float s = 0.f;
    for (int k = threadIdx.x; k < K; k += blockDim.x) { float x = vr[k]; s = fmaf(x, x, s); }
    __shared__ float red[128];
    red[threadIdx.x] = s;
    __syncthreads();
    for (int o = 64; o; o >>= 1) {
        if (threadIdx.x < o) red[threadIdx.x] += red[threadIdx.x + o];
        __syncthreads();
    }
    float scale = g[row] / sqrtf(red[0]);
    for (int k = threadIdx.x; k < K; k += blockDim.x)
        w[(size_t)row * K + k] = vr[k] * scale;
}

// ---------------------------------------------------------------------------
// bias1[j] = b1[j] + feat . w1[j, 32:]
// ---------------------------------------------------------------------------
__global__ void bias1_kernel(const float* __restrict__ feat, const float* __restrict__ w1,
                             const float* __restrict__ b1, float* __restrict__ out) {
    int j = blockIdx.x * 8 + (threadIdx.x >> 5);
    int lane = threadIdx.x & 31;
    const float* wr = w1 + (size_t)j * 2080 + 32;
    float s = 0.f;
    for (int k = lane; k < 2048; k += 32) s = fmaf(feat[k], wr[k], s);
    #pragma unroll
    for (int o = 16; o; o >>= 1) s += __shfl_down_sync(0xffffffffu, s, o);
    if (lane == 0) out[j] = b1[j] + s;
}

// ---------------------------------------------------------------------------
// TF32 tensor-core GEMM.  C[m,n] = sum_k A[m,k]*B[n,k]  (B row-major [N,K]).
// 128x128 block tile, BK=32, 8 warps (4x2), warp tile 32x64, mma m16n8k8.
// Requires M%128==0, N%128==0, K%32==0, 16B-aligned rows.
// ---------------------------------------------------------------------------
enum { EP_BIAS = 0, EP_LRELU_BIAS = 1, EP_ADD_INSIDE = 2, EP_RES_OUT = 3 };

#define BM 128
#define BN 128
#define BK 32
#define PADK 36   // 36 mod 32 == 4  ->  g*4+tg bijects 32 lanes: conflict-free LDS

__device__ __forceinline__ void cp_async16(float* s, const float* g) {
    uint32_t sa = (uint32_t)__cvta_generic_to_shared(s);
    asm volatile("cp.async.cg.shared.global [%0], [%1], 16;" :: "r"(sa), "l"(g));
}
__device__ __forceinline__ uint32_t cvt_tf32(float f) {
    uint32_t o;
    asm("cvt.rna.tf32.f32 %0, %1;" : "=r"(o) : "f"(f));
    return o;
}
__device__ __forceinline__ void mma_tf32(float* c, const uint32_t* a, const uint32_t* b) {
    asm volatile(
        "mma.sync.aligned.m16n8k8.row.col.f32.tf32.tf32.f32 "
        "{%0,%1,%2,%3}, {%4,%5,%6,%7}, {%8,%9}, {%0,%1,%2,%3};"
        : "+f"(c[0]), "+f"(c[1]), "+f"(c[2]), "+f"(c[3])
        : "r"(a[0]), "r"(a[1]), "r"(a[2]), "r"(a[3]), "r"(b[0]), "r"(b[1]));
}

template <int EP>
__global__ __launch_bounds__(256)
void gemm_tf32(const float* __restrict__ A, int lda,
               const float* __restrict__ B, int ldb,
               float* __restrict__ C, int ldc,
               const float* __restrict__ Res, int ldres,
               const float* __restrict__ bias, int K) {
    extern __shared__ float smem[];
    float* AsBase = smem;                      // [2][BM*PADK]
    float* BsBase = smem + 2 * BM * PADK;      // [2][BN*PADK]

    int tid = threadIdx.x;
    int wid = tid >> 5, lane = tid & 31;
    int g = lane >> 2, tg = lane & 3;
    int wm = (wid >> 1) * 32;
    int wn = (wid & 1) * 64;

    long brow = blockIdx.y, bcol = blockIdx.x;
    const float* Ab = A + brow * BM * (long)lda;
    const float* Bb = B + bcol * BN * (long)ldb;
    C   += brow * BM * (long)ldc   + bcol * BN;
    Res += brow * BM * (long)ldres + bcol * BN;
    const float* biasp = bias + bcol * BN;

    float acc[2][8][4];
    #pragma unroll
    for (int mt = 0; mt < 2; mt++)
        #pragma unroll
        for (int nt = 0; nt < 8; nt++)
            #pragma unroll
            for (int q = 0; q < 4; q++) acc[mt][nt][q] = 0.f;

    int T = K / BK;

    // tile loader: 1024 float4 per operand tile, 4 per thread
    auto load_tile = [&](int t, int buf) {
        const float* Ag = Ab + (long)t * BK;
        const float* Bg = Bb + (long)t * BK;
        float* as = AsBase + buf * BM * PADK;
        float* bs = BsBase + buf * BM * PADK;
        #pragma unroll
        for (int j = 0; j < 4; j++) {
            int i = tid + 256 * j;
            int r = i >> 3, k4 = (i & 7) * 4;
            cp_async16(as + r * PADK + k4, Ag + (long)r * lda + k4);
            cp_async16(bs + r * PADK + k4, Bg + (long)r * ldb + k4);
        }
        asm volatile("cp.async.commit_group;");
    };

    load_tile(0, 0);

    for (int t = 0; t < T; t++) {
        int buf = t & 1;
        asm volatile("cp.async.wait_group 0;");
        __syncthreads();
        if (t + 1 < T) load_tile(t + 1, buf ^ 1);

        const float* as = AsBase + buf * BM * PADK;
        const float* bs = BsBase + buf * BM * PADK;
        #pragma unroll
        for (int kk = 0; kk < BK; kk += 8) {
            uint32_t af[2][4], bf[8][2];
            #pragma unroll
            for (int mt = 0; mt < 2; mt++) {
                int r0 = wm + mt * 16;
                af[mt][0] = cvt_tf32(as[(r0 + g) * PADK + kk + tg]);
                af[mt][1] = cvt_tf32(as[(r0 + g + 8) * PADK + kk + tg]);
                af[mt][2] = cvt_tf32(as[(r0 + g) * PADK + kk + tg + 4]);
                af[mt][3] = cvt_tf32(as[(r0 + g + 8) * PADK + kk + tg + 4]);
            }
            #pragma unroll
            for (int nt = 0; nt < 8; nt++) {
                int c0 = wn + nt * 8;
                bf[nt][0] = cvt_tf32(bs[(c0 + g) * PADK + kk + tg]);
                bf[nt][1] = cvt_tf32(bs[(c0 + g) * PADK + kk + tg + 4]);
            }
            #pragma unroll
            for (int mt = 0; mt < 2; mt++)
                #pragma unroll
                for (int nt = 0; nt < 8; nt++)
                    mma_tf32(acc[mt][nt], af[mt], bf[nt]);
        }
        __syncthreads();
    }

    // epilogue: c0:(g, tg*2) c1:(g, tg*2+1) c2:(g+8, tg*2) c3:(g+8, tg*2+1)
    #pragma unroll
    for (int mt = 0; mt < 2; mt++) {
        #pragma unroll
        for (int half = 0; half < 2; half++) {
            long row = wm + mt * 16 + g + half * 8;
            #pragma unroll
            for (int nt = 0; nt < 8; nt++) {
                int col = wn + nt * 8 + tg * 2;
                float v0 = acc[mt][nt][half * 2 + 0];
                float v1 = acc[mt][nt][half * 2 + 1];
                if (EP == EP_BIAS) {
                    v0 += biasp[col]; v1 += biasp[col + 1];
                } else if (EP == EP_LRELU_BIAS) {
                    v0 += biasp[col]; v1 += biasp[col + 1];
                    v0 = v0 > 0.f ? v0 : 0.01f * v0;
                    v1 = v1 > 0.f ? v1 : 0.01f * v1;
                } else if (EP == EP_ADD_INSIDE) {
                    float2 r = *reinterpret_cast<const float2*>(Res + row * ldres + col);
                    v0 += r.x; v1 += r.y;
                    v0 = v0 > 0.f ? v0 : 0.01f * v0;
                    v1 = v1 > 0.f ? v1 : 0.01f * v1;
                } else {  // EP_RES_OUT
                    v0 += biasp[col]; v1 += biasp[col + 1];
                    v0 = v0 > 0.f ? v0 : 0.01f * v0;
                    v1 = v1 > 0.f ? v1 : 0.01f * v1;
                    float2 r = *reinterpret_cast<const float2*>(Res + row * ldres + col);
                    v0 += r.x; v1 += r.y;
                }
                float2 o; o.x = v0; o.y = v1;
                *reinterpret_cast<float2*>(C + row * ldc + col) = o;
            }
        }
    }
}

#define GEMM_SMEM (4 * BM * PADK * 4)   // 73728 bytes

static void launch_gemm(int ep, const float* A, int lda, const float* B, int ldb,
                        float* C, int ldc, const float* Res, int ldres,
                        const float* bias, int M, int N, int K) {
    dim3 grd(N / BN, M / BM);
    switch (ep) {
        case EP_BIAS:
            cudaFuncSetAttribute(gemm_tf32<EP_BIAS>, cudaFuncAttributeMaxDynamicSharedMemorySize, GEMM_SMEM);
            gemm_tf32<EP_BIAS><<<grd, 256, GEMM_SMEM>>>(A, lda, B, ldb, C, ldc, Res, ldres, bias, K); break;
        case EP_LRELU_BIAS:
            cudaFuncSetAttribute(gemm_tf32<EP_LRELU_BIAS>, cudaFuncAttributeMaxDynamicSharedMemorySize, GEMM_SMEM);
            gemm_tf32<EP_LRELU_BIAS><<<grd, 256, GEMM_SMEM>>>(A, lda, B, ldb, C, ldc, Res, ldres, bias, K); break;
        case EP_ADD_INSIDE:
            cudaFuncSetAttribute(gemm_tf32<EP_ADD_INSIDE>, cudaFuncAttributeMaxDynamicSharedMemorySize, GEMM_SMEM);
            gemm_tf32<EP_ADD_INSIDE><<<grd, 256, GEMM_SMEM>>>(A, lda, B, ldb, C, ldc, Res, ldres, bias, K); break;
        default:
            cudaFuncSetAttribute(gemm_tf32<EP_RES_OUT>, cudaFuncAttributeMaxDynamicSharedMemorySize, GEMM_SMEM);
            gemm_tf32<EP_RES_OUT><<<grd, 256, GEMM_SMEM>>>(A, lda, B, ldb, C, ldc, Res, ldres, bias, K); break;
    }
}

// ---------------------------------------------------------------------------
// Head
// ---------------------------------------------------------------------------
__global__ void head_kernel(const float* __restrict__ h2, const float* __restrict__ w3,
                            const float* __restrict__ b3, float* __restrict__ out) {
    __shared__ float sw[1536];
    for (int i = threadIdx.x; i < 1536; i += blockDim.x) sw[i] = w3[i];
    __syncthreads();
    int n = (blockIdx.x * blockDim.x + threadIdx.x) >> 5;
    int lane = threadIdx.x & 31;
    const float* hr = h2 + (size_t)n * 512;
    float d0 = 0.f, d1 = 0.f, d2 = 0.f;
    for (int t = lane; t < 512; t += 32) {
        float x = hr[t];
        d0 = fmaf(x, sw[t], d0);
        d1 = fmaf(x, sw[512 + t], d1);
        d2 = fmaf(x, sw[1024 + t], d2);
    }
    #pragma unroll
    for (int o = 16; o; o >>= 1) {
        d0 += __shfl_down_sync(0xffffffffu, d0, o);
        d1 += __shfl_down_sync(0xffffffffu, d1, o);
        d2 += __shfl_down_sync(0xffffffffu, d2, o);
    }
    if (lane == 0) {
        out[n]          = 1.1f / (1.f + expf(-(d0 + b3[0]))) - 0.05f;
        out[65536 + n]  = 1.1f / (1.f + expf(-(d1 + b3[1]))) - 0.05f;
        out[131072 + n] = 1.1f / (1.f + expf(-(d2 + b3[2]))) - 0.05f;
    }
}

// ---------------------------------------------------------------------------
// kernel_launch
// ---------------------------------------------------------------------------
extern "C" void kernel_launch(void* const* d_in, const int* in_sizes, int n_in,
                              void* d_out, int out_size) {
    const float* feature = (const float*)d_in[0];
    const float* cw1 = (const float*)d_in[1];  const float* cb1 = (const float*)d_in[2];
    const float* cw2 = (const float*)d_in[3];  const float* cb2 = (const float*)d_in[4];
    const float* cw3 = (const float*)d_in[5];  const float* cb3 = (const float*)d_in[6];
    const float* cw4 = (const float*)d_in[7];  const float* cb4 = (const float*)d_in[8];
    const float* cw5 = (const float*)d_in[9];  const float* cb5 = (const float*)d_in[10];
    const float* w1  = (const float*)d_in[11]; const float* b1  = (const float*)d_in[12];
    const float* m1_vf = (const float*)d_in[13]; const float* m1_gf = (const float*)d_in[14];
    const float* m1_bf = (const float*)d_in[15]; const float* m1_vg = (const float*)d_in[16];
    const float* m1_gg = (const float*)d_in[17]; const float* m1_bg = (const float*)d_in[18];
    const float* w2  = (const float*)d_in[19]; const float* b2  = (const float*)d_in[20];
    const float* m2_vf = (const float*)d_in[21]; const float* m2_gf = (const float*)d_in[22];
    const float* m2_bf = (const float*)d_in[23]; const float* m2_vg = (const float*)d_in[24];
    const float* m2_gg = (const float*)d_in[25]; const float* m2_bg = (const float*)d_in[26];
    const float* w3  = (const float*)d_in[27]; const float* b3  = (const float*)d_in[28];
    float* out = (float*)d_out;

    float *grid_, *mid, *h2, *wm1F, *wm1G, *wm2F, *wm2G, *conv0, *conv1, *feat, *bias1;
    cudaGetSymbolAddress((void**)&grid_, g_grid);
    cudaGetSymbolAddress((void**)&mid,   g_mid);
    cudaGetSymbolAddress((void**)&h2,    g_h2);
    cudaGetSymbolAddress((void**)&wm1F,  g_wm1F);
    cudaGetSymbolAddress((void**)&wm1G,  g_wm1G);
    cudaGetSymbolAddress((void**)&wm2F,  g_wm2F);
    cudaGetSymbolAddress((void**)&wm2G,  g_wm2G);
    cudaGetSymbolAddress((void**)&conv0, g_conv0);
    cudaGetSymbolAddress((void**)&conv1, g_conv1);
    cudaGetSymbolAddress((void**)&feat,  g_feat);
    cudaGetSymbolAddress((void**)&bias1, g_bias1);

    // --- positional grid features ---
    grid_kernel<<<(NPIX * 32) / 256, 256>>>(grid_);

    // --- conv stack ---
    conv3x3_kernel<<<768, 256, (448 * 9 + 256) * 4>>>(feature, cw1, cb1, conv0, 1792, 768, 8, 8, 8, 8, 1, 4);
    conv3x3_kernel<<<768, 256, (256 * 9 + 256) * 4>>>(conv0, cw2, cb2, conv1, 768, 768, 8, 8, 8, 8, 1, 3);
    conv3x3_kernel<<<768, 256, (384 * 9 + 256) * 4>>>(conv1, cw3, cb3, conv0, 768, 768, 8, 8, 8, 8, 1, 2);
    conv3x3_kernel<<<768, 256, (256 * 9 + 256) * 4>>>(conv0, cw4, cb4, conv1, 768, 768, 8, 8, 6, 6, 0, 3);
    conv3x3_kernel<<<128, 256, (768 * 9 + 256) * 4>>>(conv1, cw5, cb5, feat, 768, 128, 6, 6, 4, 4, 0, 1);

    // --- fold feat @ w1[:,32:].T + b1 into a bias vector ---
    bias1_kernel<<<128, 256>>>(feat, w1, b1, bias1);

    // --- weight-norm preprocessing ---
    wnorm_kernel<<<8 * 512, 128>>>(m1_vf, m1_gf, wm1F, 512);
    wnorm_kernel<<<8 * 512, 128>>>(m1_vg, m1_gg, wm1G, 512);
    wnorm_kernel<<<8 * 256, 128>>>(m2_vf, m2_gf, wm2F, 256);
    wnorm_kernel<<<8 * 256, 128>>>(m2_vg, m2_gg, wm2G, 256);

    // --- mid = lrelu(grid @ w1[:, :32].T + bias1)   [65536, 1024] ---
    launch_gemm(EP_LRELU_BIAS, grid_, 32, w1, 2080, mid, 1024,
                mid, 1024, bias1, NPIX, 1024, 32);

    // --- mem stack 1: halves of 1024 (512 each) ---
    for (int s = 0; s < 8; s++) {
        launch_gemm(EP_RES_OUT, mid + 512, 1024, wm1F + (size_t)s * 512 * 512, 512,
                    mid, 1024, mid, 1024, m1_bf + s * 512, NPIX, 512, 512);
        launch_gemm(EP_RES_OUT, mid, 1024, wm1G + (size_t)s * 512 * 512, 512,
                    mid + 512, 1024, mid + 512, 1024, m1_bg + s * 512, NPIX, 512, 512);
    }

    // --- h2 = lrelu(grid @ w2[:, :32].T + b2 + mid @ w2[:, 32:].T) ---
    launch_gemm(EP_BIAS, grid_, 32, w2, 1056, h2, 512, h2, 512, b2, NPIX, 512, 32);
    launch_gemm(EP_ADD_INSIDE, mid, 1024, w2 + 32, 1056, h2, 512, h2, 512, b2, NPIX, 512, 1024);

    // --- mem stack 2: halves of 512 (256 each) ---
    for (int s = 0; s < 8; s++) {
        launch_gemm(EP_RES_OUT, h2 + 256, 512, wm2F + (size_t)s * 256 * 256, 256,
                    h2, 512, h2, 512, m2_bf + s * 256, NPIX, 256, 256);
        launch_gemm(EP_RES_OUT, h2, 512, wm2G + (size_t)s * 256 * 256, 256,
                    h2 + 256, 512, h2 + 256, 512, m2_bg + s * 256, NPIX, 256, 256);
    }

    // --- head ---
    head_kernel<<<NPIX / 8, 256>>>(h2, w3, b3, out);
}

// round 4
// speedup vs baseline: 4.4315x; 1.5211x over previous
#include <cuda_runtime.h>
#include <cuda_bf16.h>
#include <cstdint>
#include <math.h>

// ---------------------------------------------------------------------------
// Scratch (static __device__ arrays; no allocation allowed)
// ---------------------------------------------------------------------------
#define NPIX 65536
__device__ __nv_bfloat16 g_grid_bf[NPIX * 64];        // [N,64] zero-padded K
__device__ float         g_mid   [NPIX * 1024];       // fp32 (residual path)
__device__ __nv_bfloat16 g_mid_bf[NPIX * 1024];       // bf16 shadow (GEMM A)
__device__ float         g_h2    [NPIX * 512];
__device__ __nv_bfloat16 g_h2_bf [NPIX * 512];
__device__ __nv_bfloat16 g_wm1F[8 * 512 * 512];
__device__ __nv_bfloat16 g_wm1G[8 * 512 * 512];
__device__ __nv_bfloat16 g_wm2F[8 * 256 * 256];
__device__ __nv_bfloat16 g_wm2G[8 * 256 * 256];
__device__ __nv_bfloat16 g_w1g_bf[1024 * 64];         // w1[:, :32] zero-padded
__device__ __nv_bfloat16 g_w2g_bf[512 * 64];          // w2[:, :32] zero-padded
__device__ __nv_bfloat16 g_w2m_bf[512 * 1024];        // w2[:, 32:]
__device__ float g_conv0[768 * 8 * 8];
__device__ float g_conv1[768 * 8 * 8];
__device__ float g_feat[2048];
__device__ float g_bias1[1024];

// ---------------------------------------------------------------------------
// Grid features -> bf16, K padded to 64 with zeros
// ---------------------------------------------------------------------------
__global__ void grid_kernel(__nv_bfloat16* __restrict__ g) {
    int idx = blockIdx.x * blockDim.x + threadIdx.x;      // n*64 + c
    int n = idx >> 6, c = idx & 63;
    float val = 0.f;
    if (c < 32) {
        int i = n >> 8, j = n & 255;
        float r = (float)(((c & 1) ? j : i) - 128) * (float)(3.14159265358979323846 / 256.0);
        float s = exp2f(0.5f * (float)(c >> 1));
        val = sinf(r * s);
    }
    g[idx] = __float2bfloat16(val);
}

// ---------------------------------------------------------------------------
// Conv / weight prep / bias fold / head (unchanged fp32 small kernels)
// ---------------------------------------------------------------------------
__global__ void conv3x3_kernel(const float* __restrict__ in, const float* __restrict__ w,
                               const float* __restrict__ bias, float* __restrict__ out,
                               int Cin, int Cout, int Hin, int Win,
                               int Hout, int Wout, int pad, int groups) {
    int oc = blockIdx.x;
    int icpg = Cin / groups;
    int ocpg = Cout / groups;
    int grp = oc / ocpg;
    extern __shared__ float sm[];
    float* sw  = sm;
    float* red = sm + icpg * 9;
    for (int i = threadIdx.x; i < icpg * 9; i += blockDim.x)
        sw[i] = w[(size_t)oc * icpg * 9 + i];
    __syncthreads();

    int icq = threadIdx.x >> 6;
    int px  = threadIdx.x & 63;
    float acc = 0.f;
    if (px < Hout * Wout) {
        int oy = px / Wout, ox = px % Wout;
        const float* inb = in + (size_t)grp * icpg * Hin * Win;
        for (int ic = icq; ic < icpg; ic += 4) {
            const float* ip = inb + (size_t)ic * Hin * Win;
            const float* wp = sw + ic * 9;
            #pragma unroll
            for (int ky = 0; ky < 3; ky++) {
                int iy = oy + ky - pad;
                if (iy < 0 || iy >= Hin) continue;
                #pragma unroll
                for (int kx = 0; kx < 3; kx++) {
                    int ix = ox + kx - pad;
                    if (ix < 0 || ix >= Win) continue;
                    acc = fmaf(ip[iy * Win + ix], wp[ky * 3 + kx], acc);
                }
            }
        }
    }
    red[icq * 64 + px] = acc;
    __syncthreads();
    if (icq == 0 && px < Hout * Wout) {
        float v = bias[oc] + red[px] + red[64 + px] + red[128 + px] + red[192 + px];
        out[(size_t)oc * Hout * Wout + px] = v > 0.f ? v : 0.01f * v;
    }
}

__global__ void wnorm_kernel(const float* __restrict__ v, const float* __restrict__ g,
                             __nv_bfloat16* __restrict__ w, int K) {
    int row = blockIdx.x;
    const float* vr = v + (size_t)row * K;
    float s = 0.f;
    for (int k = threadIdx.x; k < K; k += blockDim.x) { float x = vr[k]; s = fmaf(x, x, s); }
    __shared__ float red[128];
    red[threadIdx.x] = s;
    __syncthreads();
    for (int o = 64; o; o >>= 1) {
        if (threadIdx.x < o) red[threadIdx.x] += red[threadIdx.x + o];
        __syncthreads();
    }
    float scale = g[row] / sqrtf(red[0]);
    for (int k = threadIdx.x; k < K; k += blockDim.x)
        w[(size_t)row * K + k] = __float2bfloat16(vr[k] * scale);
}

__global__ void conv_w1g_kernel(const float* __restrict__ w1, __nv_bfloat16* __restrict__ o) {
    int idx = blockIdx.x * blockDim.x + threadIdx.x;   // 1024*64
    int j = idx >> 6, k = idx & 63;
    o[idx] = __float2bfloat16(k < 32 ? w1[(size_t)j * 2080 + k] : 0.f);
}
__global__ void conv_w2_kernel(const float* __restrict__ w2,
                               __nv_bfloat16* __restrict__ og, __nv_bfloat16* __restrict__ om) {
    int idx = blockIdx.x * blockDim.x + threadIdx.x;   // 512*1088
    int j = idx / 1088, r = idx % 1088;
    if (r < 64) og[j * 64 + r] = __float2bfloat16(r < 32 ? w2[(size_t)j * 1056 + r] : 0.f);
    else        om[(size_t)j * 1024 + (r - 64)] = __float2bfloat16(w2[(size_t)j * 1056 + 32 + (r - 64)]);
}

__global__ void bias1_kernel(const float* __restrict__ feat, const float* __restrict__ w1,
                             const float* __restrict__ b1, float* __restrict__ out) {
    int j = blockIdx.x * 8 + (threadIdx.x >> 5);
    int lane = threadIdx.x & 31;
    const float* wr = w1 + (size_t)j * 2080 + 32;
    float s = 0.f;
    for (int k = lane; k < 2048; k += 32) s = fmaf(feat[k], wr[k], s);
    #pragma unroll
    for (int o = 16; o; o >>= 1) s += __shfl_down_sync(0xffffffffu, s, o);
    if (lane == 0) out[j] = b1[j] + s;
}

__global__ void head_kernel(const float* __restrict__ h2, const float* __restrict__ w3,
                            const float* __restrict__ b3, float* __restrict__ out) {
    __shared__ float sw[1536];
    for (int i = threadIdx.x; i < 1536; i += blockDim.x) sw[i] = w3[i];
    __syncthreads();
    int n = (blockIdx.x * blockDim.x + threadIdx.x) >> 5;
    int lane = threadIdx.x & 31;
    const float* hr = h2 + (size_t)n * 512;
    float d0 = 0.f, d1 = 0.f, d2 = 0.f;
    for (int t = lane; t < 512; t += 32) {
        float x = hr[t];
        d0 = fmaf(x, sw[t], d0);
        d1 = fmaf(x, sw[512 + t], d1);
        d2 = fmaf(x, sw[1024 + t], d2);
    }
    #pragma unroll
    for (int o = 16; o; o >>= 1) {
        d0 += __shfl_down_sync(0xffffffffu, d0, o);
        d1 += __shfl_down_sync(0xffffffffu, d1, o);
        d2 += __shfl_down_sync(0xffffffffu, d2, o);
    }
    if (lane == 0) {
        out[n]          = 1.1f / (1.f + expf(-(d0 + b3[0]))) - 0.05f;
        out[65536 + n]  = 1.1f / (1.f + expf(-(d1 + b3[1]))) - 0.05f;
        out[131072 + n] = 1.1f / (1.f + expf(-(d2 + b3[2]))) - 0.05f;
    }
}

// ---------------------------------------------------------------------------
// bf16 tensor-core GEMM via mma.sync.m16n8k16 + ldmatrix + cp.async.
// C[m,n] = sum_k A[m,k]*B[n,k]; A,B bf16 row-major; C fp32 (+ optional bf16
// shadow Cbf); Res fp32. Tile 128x128xBK64, 8 warps (4x2), 4-stage pipeline.
// Requires M%128==0, N%128==0, K%64==0.
// ---------------------------------------------------------------------------
enum { EP_BIAS = 0, EP_LRELU_BIAS = 1, EP_ADD_INSIDE = 2, EP_RES_OUT = 3 };

#define BM 128
#define BN 128
#define BKB 64                    // bf16 K per tile -> 128B rows (SW128)
#define STAGES 4
#define OPB (BM * BKB * 2)        // 16 KB per operand
#define STB (2 * OPB)             // 32 KB per stage
#define GSMEM (STAGES * STB)      // 128 KB

__device__ __forceinline__ uint32_t smem_u32(const void* p) {
    uint32_t a;
    asm("{ .reg .u64 t; cvta.to.shared.u64 t, %1; cvt.u32.u64 %0, t; }" : "=r"(a) : "l"(p));
    return a;
}
__device__ __forceinline__ void cp_async16(uint32_t sa, const __nv_bfloat16* g) {
    asm volatile("cp.async.cg.shared.global [%0], [%1], 16;" :: "r"(sa), "l"(g));
}
__device__ __forceinline__ void ldsm4(uint32_t* r, uint32_t addr) {
    asm volatile("ldmatrix.sync.aligned.m8n8.x4.shared.b16 {%0,%1,%2,%3}, [%4];"
                 : "=r"(r[0]), "=r"(r[1]), "=r"(r[2]), "=r"(r[3]) : "r"(addr));
}
__device__ __forceinline__ void mma_bf16(float* c, const uint32_t* a, const uint32_t* b) {
    asm volatile(
        "mma.sync.aligned.m16n8k16.row.col.f32.bf16.bf16.f32 "
        "{%0,%1,%2,%3}, {%4,%5,%6,%7}, {%8,%9}, {%0,%1,%2,%3};"
        : "+f"(c[0]), "+f"(c[1]), "+f"(c[2]), "+f"(c[3])
        : "r"(a[0]), "r"(a[1]), "r"(a[2]), "r"(a[3]), "r"(b[0]), "r"(b[1]));
}
__device__ __forceinline__ uint32_t pack_bf16x2(float lo, float hi) {
    uint32_t u;
    asm("cvt.rn.bf16x2.f32 %0, %1, %2;" : "=r"(u) : "f"(hi), "f"(lo));
    return u;
}

template <int EP, int WBF>
__global__ __launch_bounds__(256)
void gemm_bf(const __nv_bfloat16* __restrict__ A, int lda,
             const __nv_bfloat16* __restrict__ B, int ldb,
             float* __restrict__ C, __nv_bfloat16* __restrict__ Cbf, int ldc,
             const float* __restrict__ Res, int ldres,
             const float* __restrict__ bias, int K) {
    extern __shared__ char smem[];
    uint32_t sbase = smem_u32(smem);

    int tid = threadIdx.x;
    int wid = tid >> 5, lane = tid & 31;
    int g = lane >> 2, tg = lane & 3;
    int wm = (wid >> 1) * 32;
    int wn = (wid & 1) * 64;

    long brow = blockIdx.y, bcol = blockIdx.x;
    const __nv_bfloat16* Ab = A + brow * BM * (long)lda;
    const __nv_bfloat16* Bb = B + bcol * BN * (long)ldb;
    C   += brow * BM * (long)ldc   + bcol * BN;
    if (WBF) Cbf += brow * BM * (long)ldc + bcol * BN;
    Res += brow * BM * (long)ldres + bcol * BN;
    const float* biasp = bias + bcol * BN;

    // ldmatrix per-thread address components (byte offsets into a 128x128B tile)
    uint32_t aRow[2], aXor[2], bRow[4], bXor[4];
    uint32_t akb = (lane >> 4) * 16;
    uint32_t bkb = ((lane >> 3) & 1) * 16;
    #pragma unroll
    for (int mt = 0; mt < 2; mt++) {
        uint32_t r = wm + mt * 16 + (lane & 15);
        aRow[mt] = r * 128;
        aXor[mt] = (r & 7) << 4;
    }
    #pragma unroll
    for (int p = 0; p < 4; p++) {
        uint32_t r = wn + p * 16 + ((lane >> 4) << 3) + (lane & 7);
        bRow[p] = r * 128;
        bXor[p] = (r & 7) << 4;
    }

    float acc[2][8][4];
    #pragma unroll
    for (int mt = 0; mt < 2; mt++)
        #pragma unroll
        for (int nt = 0; nt < 8; nt++)
            #pragma unroll
            for (int q = 0; q < 4; q++) acc[mt][nt][q] = 0.f;

    int T = K / BKB;

    // loader: 1024 16B-chunks per operand tile, 4 per thread
    auto load_stage = [&](int u, int s) {
        const __nv_bfloat16* Ag = Ab + u * BKB;
        const __nv_bfloat16* Bg = Bb + u * BKB;
        uint32_t sA = sbase + s * STB;
        uint32_t sB = sA + OPB;
        #pragma unroll
        for (int j = 0; j < 4; j++) {
            int idx = tid + 256 * j;
            int r = idx >> 3, c = idx & 7;
            uint32_t sw = r * 128 + ((c * 16) ^ ((r & 7) << 4));
            cp_async16(sA + sw, Ag + (long)r * lda + c * 8);
            cp_async16(sB + sw, Bg + (long)r * ldb + c * 8);
        }
    };

    // prologue: STAGES-1 committed groups
    #pragma unroll
    for (int p = 0; p < STAGES - 1; p++) {
        if (p < T) load_stage(p, p);
        asm volatile("cp.async.commit_group;");
    }

    for (int t = 0; t < T; t++) {
        asm volatile("cp.async.wait_group %0;" :: "n"(STAGES - 2));
        __syncthreads();
        int u = t + STAGES - 1;
        if (u < T) load_stage(u, u % STAGES);
        asm volatile("cp.async.commit_group;");

        uint32_t sA = sbase + (t % STAGES) * STB;
        uint32_t sB = sA + OPB;
        #pragma unroll
        for (int kk = 0; kk < 4; kk++) {
            uint32_t af[2][4], bp[4][4];
            #pragma unroll
            for (int mt = 0; mt < 2; mt++)
                ldsm4(af[mt], sA + aRow[mt] + (((kk * 32) + akb) ^ aXor[mt]));
            #pragma unroll
            for (int p = 0; p < 4; p++)
                ldsm4(bp[p], sB + bRow[p] + (((kk * 32) + bkb) ^ bXor[p]));
            #pragma unroll
            for (int mt = 0; mt < 2; mt++)
                #pragma unroll
                for (int p = 0; p < 4; p++) {
                    mma_bf16(acc[mt][p * 2 + 0], af[mt], &bp[p][0]);
                    mma_bf16(acc[mt][p * 2 + 1], af[mt], &bp[p][2]);
                }
        }
    }

    // epilogue:  c0:(g, tg*2) c1:(g, tg*2+1) c2:(g+8, tg*2) c3:(g+8, tg*2+1)
    #pragma unroll
    for (int mt = 0; mt < 2; mt++) {
        #pragma unroll
        for (int half = 0; half < 2; half++) {
            long row = wm + mt * 16 + g + half * 8;
            #pragma unroll
            for (int nt = 0; nt < 8; nt++) {
                int col = wn + nt * 8 + tg * 2;
                float v0 = acc[mt][nt][half * 2 + 0];
                float v1 = acc[mt][nt][half * 2 + 1];
                if (EP == EP_BIAS) {
                    v0 += biasp[col]; v1 += biasp[col + 1];
                } else if (EP == EP_LRELU_BIAS) {
                    v0 += biasp[col]; v1 += biasp[col + 1];
                    v0 = v0 > 0.f ? v0 : 0.01f * v0;
                    v1 = v1 > 0.f ? v1 : 0.01f * v1;
                } else if (EP == EP_ADD_INSIDE) {
                    float2 r = *reinterpret_cast<const float2*>(Res + row * ldres + col);
                    v0 += r.x; v1 += r.y;
                    v0 = v0 > 0.f ? v0 : 0.01f * v0;
                    v1 = v1 > 0.f ? v1 : 0.01f * v1;
                } else {  // EP_RES_OUT
                    v0 += biasp[col]; v1 += biasp[col + 1];
                    v0 = v0 > 0.f ? v0 : 0.01f * v0;
                    v1 = v1 > 0.f ? v1 : 0.01f * v1;
                    float2 r = *reinterpret_cast<const float2*>(Res + row * ldres + col);
                    v0 += r.x; v1 += r.y;
                }
                float2 o; o.x = v0; o.y = v1;
                *reinterpret_cast<float2*>(C + row * ldc + col) = o;
                if (WBF)
                    *reinterpret_cast<uint32_t*>(Cbf + row * ldc + col) = pack_bf16x2(v0, v1);
            }
        }
    }
}

static void launch_gemm(int ep, const __nv_bfloat16* A, int lda,
                        const __nv_bfloat16* B, int ldb,
                        float* C, __nv_bfloat16* Cbf, int ldc,
                        const float* Res, int ldres,
                        const float* bias, int M, int N, int K) {
    dim3 grd(N / BN, M / BM);
    switch (ep) {
        case EP_BIAS:
            cudaFuncSetAttribute(gemm_bf<EP_BIAS, 0>, cudaFuncAttributeMaxDynamicSharedMemorySize, GSMEM);
            gemm_bf<EP_BIAS, 0><<<grd, 256, GSMEM>>>(A, lda, B, ldb, C, Cbf, ldc, Res, ldres, bias, K); break;
        case EP_LRELU_BIAS:
            cudaFuncSetAttribute(gemm_bf<EP_LRELU_BIAS, 1>, cudaFuncAttributeMaxDynamicSharedMemorySize, GSMEM);
            gemm_bf<EP_LRELU_BIAS, 1><<<grd, 256, GSMEM>>>(A, lda, B, ldb, C, Cbf, ldc, Res, ldres, bias, K); break;
        case EP_ADD_INSIDE:
            cudaFuncSetAttribute(gemm_bf<EP_ADD_INSIDE, 1>, cudaFuncAttributeMaxDynamicSharedMemorySize, GSMEM);
            gemm_bf<EP_ADD_INSIDE, 1><<<grd, 256, GSMEM>>>(A, lda, B, ldb, C, Cbf, ldc, Res, ldres, bias, K); break;
        default:
            cudaFuncSetAttribute(gemm_bf<EP_RES_OUT, 1>, cudaFuncAttributeMaxDynamicSharedMemorySize, GSMEM);
            gemm_bf<EP_RES_OUT, 1><<<grd, 256, GSMEM>>>(A, lda, B, ldb, C, Cbf, ldc, Res, ldres, bias, K); break;
    }
}

// ---------------------------------------------------------------------------
// kernel_launch
// ---------------------------------------------------------------------------
extern "C" void kernel_launch(void* const* d_in, const int* in_sizes, int n_in,
                              void* d_out, int out_size) {
    const float* feature = (const float*)d_in[0];
    const float* cw1 = (const float*)d_in[1];  const float* cb1 = (const float*)d_in[2];
    const float* cw2 = (const float*)d_in[3];  const float* cb2 = (const float*)d_in[4];
    const float* cw3 = (const float*)d_in[5];  const float* cb3 = (const float*)d_in[6];
    const float* cw4 = (const float*)d_in[7];  const float* cb4 = (const float*)d_in[8];
    const float* cw5 = (const float*)d_in[9];  const float* cb5 = (const float*)d_in[10];
    const float* w1  = (const float*)d_in[11]; const float* b1  = (const float*)d_in[12];
    const float* m1_vf = (const float*)d_in[13]; const float* m1_gf = (const float*)d_in[14];
    const float* m1_bf = (const float*)d_in[15]; const float* m1_vg = (const float*)d_in[16];
    const float* m1_gg = (const float*)d_in[17]; const float* m1_bg = (const float*)d_in[18];
    const float* w2  = (const float*)d_in[19]; const float* b2  = (const float*)d_in[20];
    const float* m2_vf = (const float*)d_in[21]; const float* m2_gf = (const float*)d_in[22];
    const float* m2_bf = (const float*)d_in[23]; const float* m2_vg = (const float*)d_in[24];
    const float* m2_gg = (const float*)d_in[25]; const float* m2_bg = (const float*)d_in[26];
    const float* w3  = (const float*)d_in[27]; const float* b3  = (const float*)d_in[28];
    float* out = (float*)d_out;

    __nv_bfloat16 *grid_bf, *mid_bf, *h2_bf, *wm1F, *wm1G, *wm2F, *wm2G, *w1g, *w2g, *w2m;
    float *mid, *h2, *conv0, *conv1, *feat, *bias1;
    cudaGetSymbolAddress((void**)&grid_bf, g_grid_bf);
    cudaGetSymbolAddress((void**)&mid,     g_mid);
    cudaGetSymbolAddress((void**)&mid_bf,  g_mid_bf);
    cudaGetSymbolAddress((void**)&h2,      g_h2);
    cudaGetSymbolAddress((void**)&h2_bf,   g_h2_bf);
    cudaGetSymbolAddress((void**)&wm1F,    g_wm1F);
    cudaGetSymbolAddress((void**)&wm1G,    g_wm1G);
    cudaGetSymbolAddress((void**)&wm2F,    g_wm2F);
    cudaGetSymbolAddress((void**)&wm2G,    g_wm2G);
    cudaGetSymbolAddress((void**)&w1g,     g_w1g_bf);
    cudaGetSymbolAddress((void**)&w2g,     g_w2g_bf);
    cudaGetSymbolAddress((void**)&w2m,     g_w2m_bf);
    cudaGetSymbolAddress((void**)&conv0,   g_conv0);
    cudaGetSymbolAddress((void**)&conv1,   g_conv1);
    cudaGetSymbolAddress((void**)&feat,    g_feat);
    cudaGetSymbolAddress((void**)&bias1,   g_bias1);

    // --- positional grid features (bf16, K padded to 64) ---
    grid_kernel<<<(NPIX * 64) / 256, 256>>>(grid_bf);

    // --- conv stack ---
    conv3x3_kernel<<<768, 256, (448 * 9 + 256) * 4>>>(feature, cw1, cb1, conv0, 1792, 768, 8, 8, 8, 8, 1, 4);
    conv3x3_kernel<<<768, 256, (256 * 9 + 256) * 4>>>(conv0, cw2, cb2, conv1, 768, 768, 8, 8, 8, 8, 1, 3);
    conv3x3_kernel<<<768, 256, (384 * 9 + 256) * 4>>>(conv1, cw3, cb3, conv0, 768, 768, 8, 8, 8, 8, 1, 2);
    conv3x3_kernel<<<768, 256, (256 * 9 + 256) * 4>>>(conv0, cw4, cb4, conv1, 768, 768, 8, 8, 6, 6, 0, 3);
    conv3x3_kernel<<<128, 256, (768 * 9 + 256) * 4>>>(conv1, cw5, cb5, feat, 768, 128, 6, 6, 4, 4, 0, 1);

    // --- fold feat @ w1[:,32:].T + b1 into a bias vector ---
    bias1_kernel<<<128, 256>>>(feat, w1, b1, bias1);

    // --- weight prep (bf16) ---
    wnorm_kernel<<<8 * 512, 128>>>(m1_vf, m1_gf, wm1F, 512);
    wnorm_kernel<<<8 * 512, 128>>>(m1_vg, m1_gg, wm1G, 512);
    wnorm_kernel<<<8 * 256, 128>>>(m2_vf, m2_gf, wm2F, 256);
    wnorm_kernel<<<8 * 256, 128>>>(m2_vg, m2_gg, wm2G, 256);
    conv_w1g_kernel<<<(1024 * 64) / 256, 256>>>(w1, w1g);
    conv_w2_kernel<<<(512 * 1088) / 256, 256>>>(w2, w2g, w2m);

    // --- mid = lrelu(grid @ w1grid.T + bias1)   [65536, 1024] ---
    launch_gemm(EP_LRELU_BIAS, grid_bf, 64, w1g, 64, mid, mid_bf, 1024,
                mid, 1024, bias1, NPIX, 1024, 64);

    // --- mem stack 1: halves of 1024 (512 each) ---
    for (int s = 0; s < 8; s++) {
        launch_gemm(EP_RES_OUT, mid_bf + 512, 1024, wm1F + (size_t)s * 512 * 512, 512,
                    mid, mid_bf, 1024, mid, 1024, m1_bf + s * 512, NPIX, 512, 512);
        launch_gemm(EP_RES_OUT, mid_bf, 1024, wm1G + (size_t)s * 512 * 512, 512,
                    mid + 512, mid_bf + 512, 1024, mid + 512, 1024, m1_bg + s * 512, NPIX, 512, 512);
    }

    // --- h2 = lrelu(grid @ w2grid.T + b2 + mid @ w2mid.T) ---
    launch_gemm(EP_BIAS, grid_bf, 64, w2g, 64, h2, (__nv_bfloat16*)0, 512,
                h2, 512, b2, NPIX, 512, 64);
    launch_gemm(EP_ADD_INSIDE, mid_bf, 1024, w2m, 1024, h2, h2_bf, 512,
                h2, 512, b2, NPIX, 512, 1024);

    // --- mem stack 2: halves of 512 (256 each) ---
    for (int s = 0; s < 8; s++) {
        launch_gemm(EP_RES_OUT, h2_bf + 256, 512, wm2F + (size_t)s * 256 * 256, 256,
                    h2, h2_bf, 512, h2, 512, m2_bf + s * 256, NPIX, 256, 256);
        launch_gemm(EP_RES_OUT, h2_bf, 512, wm2G + (size_t)s * 256 * 256, 256,
                    h2 + 256, h2_bf + 256, 512, h2 + 256, 512, m2_bg + s * 256, NPIX, 256, 256);
    }

    // --- head ---
    head_kernel<<<NPIX / 8, 256>>>(h2, w3, b3, out);
}

// round 7
// speedup vs baseline: 4.4410x; 1.0021x over previous
#include <cuda_runtime.h>
#include <cuda_bf16.h>
#include <cstdint>
#include <math.h>

// ---------------------------------------------------------------------------
// Scratch
// ---------------------------------------------------------------------------
#define NPIX 65536
// concatenated bf16 activations: [grid(64, zero-padded) | mid(1024)]
__device__ __nv_bfloat16 g_cat[NPIX * 1088];
__device__ float         g_mid [NPIX * 1024];         // fp32 residual path
__device__ float         g_h2  [NPIX * 512];
__device__ __nv_bfloat16 g_h2_bf[NPIX * 512];
__device__ __nv_bfloat16 g_wm1F[8 * 512 * 512];
__device__ __nv_bfloat16 g_wm1G[8 * 512 * 512];
__device__ __nv_bfloat16 g_wm2F[8 * 256 * 256];
__device__ __nv_bfloat16 g_wm2G[8 * 256 * 256];
__device__ __nv_bfloat16 g_w1g_bf[1024 * 64];         // w1[:, :32] zero-padded
__device__ __nv_bfloat16 g_w2cat[512 * 1088];         // [w2grid(64pad) | w2mid(1024)]
__device__ float g_conv0[768 * 8 * 8];
__device__ float g_conv1[768 * 8 * 8];
__device__ float g_feat[2048];
__device__ float g_bias1[1024];

// ---------------------------------------------------------------------------
// Grid features -> bf16 into g_cat cols [0,64), stride 1088
// ---------------------------------------------------------------------------
__global__ void grid_kernel(__nv_bfloat16* __restrict__ cat) {
    int idx = blockIdx.x * blockDim.x + threadIdx.x;      // n*64 + c
    int n = idx >> 6, c = idx & 63;
    float val = 0.f;
    if (c < 32) {
        int i = n >> 8, j = n & 255;
        float r = (float)(((c & 1) ? j : i) - 128) * (float)(3.14159265358979323846 / 256.0);
        float s = exp2f(0.5f * (float)(c >> 1));
        val = sinf(r * s);
    }
    cat[(size_t)n * 1088 + c] = __float2bfloat16(val);
}

// ---------------------------------------------------------------------------
// Conv / weight prep / bias fold / head
// ---------------------------------------------------------------------------
__global__ void conv3x3_kernel(const float* __restrict__ in, const float* __restrict__ w,
                               const float* __restrict__ bias, float* __restrict__ out,
                               int Cin, int Cout, int Hin, int Win,
                               int Hout, int Wout, int pad, int groups) {
    int oc = blockIdx.x;
    int icpg = Cin / groups;
    int ocpg = Cout / groups;
    int grp = oc / ocpg;
    extern __shared__ float sm[];
    float* sw  = sm;
    float* red = sm + icpg * 9;
    for (int i = threadIdx.x; i < icpg * 9; i += blockDim.x)
        sw[i] = w[(size_t)oc * icpg * 9 + i];
    __syncthreads();

    int icq = threadIdx.x >> 6;
    int px  = threadIdx.x & 63;
    float acc = 0.f;
    if (px < Hout * Wout) {
        int oy = px / Wout, ox = px % Wout;
        const float* inb = in + (size_t)grp * icpg * Hin * Win;
        for (int ic = icq; ic < icpg; ic += 4) {
            const float* ip = inb + (size_t)ic * Hin * Win;
            const float* wp = sw + ic * 9;
            #pragma unroll
            for (int ky = 0; ky < 3; ky++) {
                int iy = oy + ky - pad;
                if (iy < 0 || iy >= Hin) continue;
                #pragma unroll
                for (int kx = 0; kx < 3; kx++) {
                    int ix = ox + kx - pad;
                    if (ix < 0 || ix >= Win) continue;
                    acc = fmaf(ip[iy * Win + ix], wp[ky * 3 + kx], acc);
                }
            }
        }
    }
    red[icq * 64 + px] = acc;
    __syncthreads();
    if (icq == 0 && px < Hout * Wout) {
        float v = bias[oc] + red[px] + red[64 + px] + red[128 + px] + red[192 + px];
        out[(size_t)oc * Hout * Wout + px] = v > 0.f ? v : 0.01f * v;
    }
}

__global__ void wnorm_kernel(const float* __restrict__ v, const float* __restrict__ g,
                             __nv_bfloat16* __restrict__ w, int K) {
    int row = blockIdx.x;
    const float* vr = v + (size_t)row * K;
    float s = 0.f;
    for (int k = threadIdx.x; k < K; k += blockDim.x) { float x = vr[k]; s = fmaf(x, x, s); }
    __shared__ float red[128];
    red[threadIdx.x] = s;
    __syncthreads();
    for (int o = 64; o; o >>= 1) {
        if (threadIdx.x < o) red[threadIdx.x] += red[threadIdx.x + o];
        __syncthreads();
    }
    float scale = g[row] / sqrtf(red[0]);
    for (int k = threadIdx.x; k < K; k += blockDim.x)
        w[(size_t)row * K + k] = __float2bfloat16(vr[k] * scale);
}

__global__ void conv_w1g_kernel(const float* __restrict__ w1, __nv_bfloat16* __restrict__ o) {
    int idx = blockIdx.x * blockDim.x + threadIdx.x;   // 1024*64
    int j = idx >> 6, k = idx & 63;
    o[idx] = __float2bfloat16(k < 32 ? w1[(size_t)j * 2080 + k] : 0.f);
}
__global__ void conv_w2cat_kernel(const float* __restrict__ w2, __nv_bfloat16* __restrict__ o) {
    int idx = blockIdx.x * blockDim.x + threadIdx.x;   // 512*1088
    int j = idx / 1088, r = idx % 1088;
    float v;
    if (r < 32)       v = w2[(size_t)j * 1056 + r];
    else if (r < 64)  v = 0.f;
    else              v = w2[(size_t)j * 1056 + 32 + (r - 64)];
    o[idx] = __float2bfloat16(v);
}

__global__ void bias1_kernel(const float* __restrict__ feat, const float* __restrict__ w1,
                             const float* __restrict__ b1, float* __restrict__ out) {
    int j = blockIdx.x * 8 + (threadIdx.x >> 5);
    int lane = threadIdx.x & 31;
    const float* wr = w1 + (size_t)j * 2080 + 32;
    float s = 0.f;
    for (int k = lane; k < 2048; k += 32) s = fmaf(feat[k], wr[k], s);
    #pragma unroll
    for (int o = 16; o; o >>= 1) s += __shfl_down_sync(0xffffffffu, s, o);
    if (lane == 0) out[j] = b1[j] + s;
}

__global__ void head_kernel(const float* __restrict__ h2, const float* __restrict__ w3,
                            const float* __restrict__ b3, float* __restrict__ out) {
    __shared__ float sw[1536];
    for (int i = threadIdx.x; i < 1536; i += blockDim.x) sw[i] = w3[i];
    __syncthreads();
    int n = (blockIdx.x * blockDim.x + threadIdx.x) >> 5;
    int lane = threadIdx.x & 31;
    const float* hr = h2 + (size_t)n * 512;
    float d0 = 0.f, d1 = 0.f, d2 = 0.f;
    for (int t = lane; t < 512; t += 32) {
        float x = hr[t];
        d0 = fmaf(x, sw[t], d0);
        d1 = fmaf(x, sw[512 + t], d1);
        d2 = fmaf(x, sw[1024 + t], d2);
    }
    #pragma unroll
    for (int o = 16; o; o >>= 1) {
        d0 += __shfl_down_sync(0xffffffffu, d0, o);
        d1 += __shfl_down_sync(0xffffffffu, d1, o);
        d2 += __shfl_down_sync(0xffffffffu, d2, o);
    }
    if (lane == 0) {
        out[n]          = 1.1f / (1.f + expf(-(d0 + b3[0]))) - 0.05f;
        out[65536 + n]  = 1.1f / (1.f + expf(-(d1 + b3[1]))) - 0.05f;
        out[131072 + n] = 1.1f / (1.f + expf(-(d2 + b3[2]))) - 0.05f;
    }
}

// ---------------------------------------------------------------------------
// bf16 GEMM: mma.sync.m16n8k16 + ldmatrix + cp.async.
// 128x128 CTA tile, 8 warps (4x2), warp tile 32x64, BK=64, 3 stages (96KB),
// 256 threads -> 2 CTAs/SM.  C fp32 (+ optional bf16 shadow, own stride).
// Same fragment addressing as the round-4 kernel that PASSED on hardware.
// ---------------------------------------------------------------------------
enum { EP_LRELU_BIAS = 1, EP_RES_OUT = 3 };

#define BM 128
#define BN 128
#define BKB 64
#define STAGES 3
#define OPB (BM * BKB * 2)        // 16 KB
#define STB (2 * OPB)             // 32 KB
#define GSMEM (STAGES * STB)      // 96 KB

__device__ __forceinline__ uint32_t smem_u32(const void* p) {
    uint32_t a;
    asm("{ .reg .u64 t; cvta.to.shared.u64 t, %1; cvt.u32.u64 %0, t; }" : "=r"(a) : "l"(p));
    return a;
}
__device__ __forceinline__ void cp_async16(uint32_t sa, const __nv_bfloat16* g) {
    asm volatile("cp.async.cg.shared.global [%0], [%1], 16;" :: "r"(sa), "l"(g));
}
__device__ __forceinline__ void ldsm4(uint32_t* r, uint32_t addr) {
    asm volatile("ldmatrix.sync.aligned.m8n8.x4.shared.b16 {%0,%1,%2,%3}, [%4];"
                 : "=r"(r[0]), "=r"(r[1]), "=r"(r[2]), "=r"(r[3]) : "r"(addr));
}
__device__ __forceinline__ void mma_bf16(float* c, const uint32_t* a, const uint32_t* b) {
    asm volatile(
        "mma.sync.aligned.m16n8k16.row.col.f32.bf16.bf16.f32 "
        "{%0,%1,%2,%3}, {%4,%5,%6,%7}, {%8,%9}, {%0,%1,%2,%3};"
        : "+f"(c[0]), "+f"(c[1]), "+f"(c[2]), "+f"(c[3])
        : "r"(a[0]), "r"(a[1]), "r"(a[2]), "r"(a[3]), "r"(b[0]), "r"(b[1]));
}
__device__ __forceinline__ uint32_t pack_bf16x2(float lo, float hi) {
    uint32_t u;
    asm("cvt.rn.bf16x2.f32 %0, %1, %2;" : "=r"(u) : "f"(hi), "f"(lo));
    return u;
}

template <int EP, int WBF>
__global__ __launch_bounds__(256)
void gemm_bf(const __nv_bfloat16* __restrict__ A, int lda,
             const __nv_bfloat16* __restrict__ B, int ldb,
             float* __restrict__ C, int ldc,
             __nv_bfloat16* __restrict__ Cbf, int ldcbf,
             const float* __restrict__ Res, int ldres,
             const float* __restrict__ bias, int K) {
    extern __shared__ char smem[];
    uint32_t sbase = smem_u32(smem);

    int tid = threadIdx.x;
    int wid = tid >> 5, lane = tid & 31;
    int g = lane >> 2, tg = lane & 3;
    int wm = (wid >> 1) * 32;
    int wn = (wid & 1) * 64;

    long brow = blockIdx.y, bcol = blockIdx.x;
    const __nv_bfloat16* Ab = A + brow * BM * (long)lda;
    const __nv_bfloat16* Bb = B + bcol * BN * (long)ldb;
    C   += brow * BM * (long)ldc   + bcol * BN;
    if (WBF) Cbf += brow * BM * (long)ldcbf + bcol * BN;
    Res += brow * BM * (long)ldres + bcol * BN;
    const float* biasp = bias + bcol * BN;

    // ldmatrix address components (byte offsets within 128-row x 128B tile)
    uint32_t aRow[2], aXor[2], bRow[4], bXor[4];
    uint32_t akb = (lane >> 4) * 16;
    uint32_t bkb = ((lane >> 3) & 1) * 16;
    #pragma unroll
    for (int mt = 0; mt < 2; mt++) {
        uint32_t r = wm + mt * 16 + (lane & 15);
        aRow[mt] = r * 128;
        aXor[mt] = (r & 7) << 4;
    }
    #pragma unroll
    for (int p = 0; p < 4; p++) {
        uint32_t r = wn + p * 16 + ((lane >> 4) << 3) + (lane & 7);
        bRow[p] = r * 128;
        bXor[p] = (r & 7) << 4;
    }

    float acc[2][8][4];
    #pragma unroll
    for (int mt = 0; mt < 2; mt++)
        #pragma unroll
        for (int nt = 0; nt < 8; nt++)
            #pragma unroll
            for (int q = 0; q < 4; q++) acc[mt][nt][q] = 0.f;

    int T = K / BKB;

    // loader: 1024 16B-chunks per operand tile, 4 per thread per operand
    auto load_stage = [&](int u, int st) {
        const __nv_bfloat16* Ag = Ab + u * BKB;
        const __nv_bfloat16* Bg = Bb + u * BKB;
        uint32_t sA = sbase + st * STB;
        uint32_t sB = sA + OPB;
        #pragma unroll
        for (int j = 0; j < 4; j++) {
            int idx = tid + 256 * j;
            int r = idx >> 3, c = idx & 7;
            uint32_t sw = r * 128 + ((c * 16) ^ ((r & 7) << 4));
            cp_async16(sA + sw, Ag + (long)r * lda + c * 8);
            cp_async16(sB + sw, Bg + (long)r * ldb + c * 8);
        }
    };

    #pragma unroll
    for (int p = 0; p < STAGES - 1; p++) {
        if (p < T) load_stage(p, p);
        asm volatile("cp.async.commit_group;");
    }

    for (int t = 0; t < T; t++) {
        asm volatile("cp.async.wait_group %0;" :: "n"(STAGES - 2));
        __syncthreads();
        int u = t + STAGES - 1;
        if (u < T) load_stage(u, u % STAGES);
        asm volatile("cp.async.commit_group;");

        uint32_t sA = sbase + (t % STAGES) * STB;
        uint32_t sB = sA + OPB;
        #pragma unroll
        for (int kk = 0; kk < 4; kk++) {
            uint32_t af[2][4], bp[4][4];
            #pragma unroll
            for (int mt = 0; mt < 2; mt++)
                ldsm4(af[mt], sA + aRow[mt] + (((kk * 32) + akb) ^ aXor[mt]));
            #pragma unroll
            for (int p = 0; p < 4; p++)
                ldsm4(bp[p], sB + bRow[p] + (((kk * 32) + bkb) ^ bXor[p]));
            #pragma unroll
            for (int mt = 0; mt < 2; mt++)
                #pragma unroll
                for (int p = 0; p < 4; p++) {
                    mma_bf16(acc[mt][p * 2 + 0], af[mt], &bp[p][0]);
                    mma_bf16(acc[mt][p * 2 + 1], af[mt], &bp[p][2]);
                }
        }
    }

    // epilogue
    #pragma unroll
    for (int mt = 0; mt < 2; mt++) {
        #pragma unroll
        for (int half = 0; half < 2; half++) {
            long row = wm + mt * 16 + g + half * 8;
            #pragma unroll
            for (int nt = 0; nt < 8; nt++) {
                int col = wn + nt * 8 + tg * 2;
                float v0 = acc[mt][nt][half * 2 + 0];
                float v1 = acc[mt][nt][half * 2 + 1];
                if (EP == EP_LRELU_BIAS) {
                    v0 += biasp[col]; v1 += biasp[col + 1];
                    v0 = v0 > 0.f ? v0 : 0.01f * v0;
                    v1 = v1 > 0.f ? v1 : 0.01f * v1;
                } else {  // EP_RES_OUT
                    v0 += biasp[col]; v1 += biasp[col + 1];
                    v0 = v0 > 0.f ? v0 : 0.01f * v0;
                    v1 = v1 > 0.f ? v1 : 0.01f * v1;
                    float2 r = *reinterpret_cast<const float2*>(Res + row * ldres + col);
                    v0 += r.x; v1 += r.y;
                }
                float2 o; o.x = v0; o.y = v1;
                *reinterpret_cast<float2*>(C + row * ldc + col) = o;
                if (WBF)
                    *reinterpret_cast<uint32_t*>(Cbf + row * ldcbf + col) = pack_bf16x2(v0, v1);
            }
        }
    }
}

static void launch_gemm(int ep, const __nv_bfloat16* A, int lda,
                        const __nv_bfloat16* B, int ldb,
                        float* C, int ldc, __nv_bfloat16* Cbf, int ldcbf,
                        const float* Res, int ldres,
                        const float* bias, int M, int N, int K) {
    dim3 grd(N / BN, M / BM);
    if (ep == EP_LRELU_BIAS) {
        if (Cbf) {
            cudaFuncSetAttribute(gemm_bf<EP_LRELU_BIAS, 1>, cudaFuncAttributeMaxDynamicSharedMemorySize, GSMEM);
            gemm_bf<EP_LRELU_BIAS, 1><<<grd, 256, GSMEM>>>(A, lda, B, ldb, C, ldc, Cbf, ldcbf, Res, ldres, bias, K);
        } else {
            cudaFuncSetAttribute(gemm_bf<EP_LRELU_BIAS, 0>, cudaFuncAttributeMaxDynamicSharedMemorySize, GSMEM);
            gemm_bf<EP_LRELU_BIAS, 0><<<grd, 256, GSMEM>>>(A, lda, B, ldb, C, ldc, Cbf, ldcbf, Res, ldres, bias, K);
        }
    } else {
        cudaFuncSetAttribute(gemm_bf<EP_RES_OUT, 1>, cudaFuncAttributeMaxDynamicSharedMemorySize, GSMEM);
        gemm_bf<EP_RES_OUT, 1><<<grd, 256, GSMEM>>>(A, lda, B, ldb, C, ldc, Cbf, ldcbf, Res, ldres, bias, K);
    }
}

// ---------------------------------------------------------------------------
// kernel_launch
// ---------------------------------------------------------------------------
extern "C" void kernel_launch(void* const* d_in, const int* in_sizes, int n_in,
                              void* d_out, int out_size) {
    const float* feature = (const float*)d_in[0];
    const float* cw1 = (const float*)d_in[1];  const float* cb1 = (const float*)d_in[2];
    const float* cw2 = (const float*)d_in[3];  const float* cb2 = (const float*)d_in[4];
    const float* cw3 = (const float*)d_in[5];  const float* cb3 = (const float*)d_in[6];
    const float* cw4 = (const float*)d_in[7];  const float* cb4 = (const float*)d_in[8];
    const float* cw5 = (const float*)d_in[9];  const float* cb5 = (const float*)d_in[10];
    const float* w1  = (const float*)d_in[11]; const float* b1  = (const float*)d_in[12];
    const float* m1_vf = (const float*)d_in[13]; const float* m1_gf = (const float*)d_in[14];
    const float* m1_bf = (const float*)d_in[15]; const float* m1_vg = (const float*)d_in[16];
    const float* m1_gg = (const float*)d_in[17]; const float* m1_bg = (const float*)d_in[18];
    const float* w2  = (const float*)d_in[19]; const float* b2  = (const float*)d_in[20];
    const float* m2_vf = (const float*)d_in[21]; const float* m2_gf = (const float*)d_in[22];
    const float* m2_bf = (const float*)d_in[23]; const float* m2_vg = (const float*)d_in[24];
    const float* m2_gg = (const float*)d_in[25]; const float* m2_bg = (const float*)d_in[26];
    const float* w3  = (const float*)d_in[27]; const float* b3  = (const float*)d_in[28];
    float* out = (float*)d_out;

    __nv_bfloat16 *cat, *h2_bf, *wm1F, *wm1G, *wm2F, *wm2G, *w1g, *w2c;
    float *mid, *h2, *conv0, *conv1, *feat, *bias1;
    cudaGetSymbolAddress((void**)&cat,   g_cat);
    cudaGetSymbolAddress((void**)&mid,   g_mid);
    cudaGetSymbolAddress((void**)&h2,    g_h2);
    cudaGetSymbolAddress((void**)&h2_bf, g_h2_bf);
    cudaGetSymbolAddress((void**)&wm1F,  g_wm1F);
    cudaGetSymbolAddress((void**)&wm1G,  g_wm1G);
    cudaGetSymbolAddress((void**)&wm2F,  g_wm2F);
    cudaGetSymbolAddress((void**)&wm2G,  g_wm2G);
    cudaGetSymbolAddress((void**)&w1g,   g_w1g_bf);
    cudaGetSymbolAddress((void**)&w2c,   g_w2cat);
    cudaGetSymbolAddress((void**)&conv0, g_conv0);
    cudaGetSymbolAddress((void**)&conv1, g_conv1);
    cudaGetSymbolAddress((void**)&feat,  g_feat);
    cudaGetSymbolAddress((void**)&bias1, g_bias1);

    // --- positional grid features into cat[:, 0:64] ---
    grid_kernel<<<(NPIX * 64) / 256, 256>>>(cat);

    // --- conv stack ---
    conv3x3_kernel<<<768, 256, (448 * 9 + 256) * 4>>>(feature, cw1, cb1, conv0, 1792, 768, 8, 8, 8, 8, 1, 4);
    conv3x3_kernel<<<768, 256, (256 * 9 + 256) * 4>>>(conv0, cw2, cb2, conv1, 768, 768, 8, 8, 8, 8, 1, 3);
    conv3x3_kernel<<<768, 256, (384 * 9 + 256) * 4>>>(conv1, cw3, cb3, conv0, 768, 768, 8, 8, 8, 8, 1, 2);
    conv3x3_kernel<<<768, 256, (256 * 9 + 256) * 4>>>(conv0, cw4, cb4, conv1, 768, 768, 8, 8, 6, 6, 0, 3);
    conv3x3_kernel<<<128, 256, (768 * 9 + 256) * 4>>>(conv1, cw5, cb5, feat, 768, 128, 6, 6, 4, 4, 0, 1);

    // --- fold feat @ w1[:,32:].T + b1 into a bias vector ---
    bias1_kernel<<<128, 256>>>(feat, w1, b1, bias1);

    // --- weight prep (bf16) ---
    wnorm_kernel<<<8 * 512, 128>>>(m1_vf, m1_gf, wm1F, 512);
    wnorm_kernel<<<8 * 512, 128>>>(m1_vg, m1_gg, wm1G, 512);
    wnorm_kernel<<<8 * 256, 128>>>(m2_vf, m2_gf, wm2F, 256);
    wnorm_kernel<<<8 * 256, 128>>>(m2_vg, m2_gg, wm2G, 256);
    conv_w1g_kernel<<<(1024 * 64) / 256, 256>>>(w1, w1g);
    conv_w2cat_kernel<<<(512 * 1088) / 256, 256>>>(w2, w2c);

    // --- mid = lrelu(grid @ w1grid.T + bias1): A = cat[:,0:64] ---
    launch_gemm(EP_LRELU_BIAS, cat, 1088, w1g, 64, mid, 1024, cat + 64, 1088,
                mid, 1024, bias1, NPIX, 1024, 64);

    // --- mem stack 1: halves of 1024 inside cat[:,64:1088] + fp32 mid ---
    for (int s = 0; s < 8; s++) {
        launch_gemm(EP_RES_OUT, cat + 64 + 512, 1088, wm1F + (size_t)s * 512 * 512, 512,
                    mid, 1024, cat + 64, 1088, mid, 1024, m1_bf + s * 512, NPIX, 512, 512);
        launch_gemm(EP_RES_OUT, cat + 64, 1088, wm1G + (size_t)s * 512 * 512, 512,
                    mid + 512, 1024, cat + 64 + 512, 1088, mid + 512, 1024, m1_bg + s * 512, NPIX, 512, 512);
    }

    // --- h2 = lrelu(cat @ w2cat.T + b2): single K=1088 GEMM ---
    launch_gemm(EP_LRELU_BIAS, cat, 1088, w2c, 1088, h2, 512, h2_bf, 512,
                h2, 512, b2, NPIX, 512, 1088);

    // --- mem stack 2: halves of 512 (256 each) ---
    for (int s = 0; s < 8; s++) {
        launch_gemm(EP_RES_OUT, h2_bf + 256, 512, wm2F + (size_t)s * 256 * 256, 256,
                    h2, 512, h2_bf, 512, h2, 512, m2_bf + s * 256, NPIX, 256, 256);
        launch_gemm(EP_RES_OUT, h2_bf, 512, wm2G + (size_t)s * 256 * 256, 256,
                    h2 + 256, 512, h2_bf + 256, 512, h2 + 256, 512, m2_bg + s * 256, NPIX, 256, 256);
    }

    // --- head ---
    head_kernel<<<NPIX / 8, 256>>>(h2, w3, b3, out);
}

// round 8
// speedup vs baseline: 5.2375x; 1.1794x over previous
#include <cuda_runtime.h>
#include <cuda_bf16.h>
#include <cstdint>
#include <math.h>

// ---------------------------------------------------------------------------
// Scratch
// ---------------------------------------------------------------------------
#define NPIX 65536
// concatenated bf16 activations: [grid(64, zero-padded) | mid(1024)]
__device__ __nv_bfloat16 g_cat[NPIX * 1088];
__device__ float         g_mid [NPIX * 1024];         // fp32 residual path
__device__ float         g_h2  [NPIX * 512];
__device__ __nv_bfloat16 g_h2_bf[NPIX * 512];
__device__ __nv_bfloat16 g_wm1F[8 * 512 * 512];
__device__ __nv_bfloat16 g_wm1G[8 * 512 * 512];
__device__ __nv_bfloat16 g_wm2F[8 * 256 * 256];
__device__ __nv_bfloat16 g_wm2G[8 * 256 * 256];
__device__ __nv_bfloat16 g_w1g_bf[1024 * 64];         // w1[:, :32] zero-padded
__device__ __nv_bfloat16 g_w2cat[512 * 1088];         // [w2grid(64pad) | w2mid(1024)]
__device__ float g_conv0[768 * 8 * 8];
__device__ float g_conv1[768 * 8 * 8];
__device__ float g_feat[2048];
__device__ float g_bias1[1024];

// ---------------------------------------------------------------------------
// Grid features -> bf16 into g_cat cols [0,64), stride 1088
// ---------------------------------------------------------------------------
__global__ void grid_kernel(__nv_bfloat16* __restrict__ cat) {
    int idx = blockIdx.x * blockDim.x + threadIdx.x;      // n*64 + c
    int n = idx >> 6, c = idx & 63;
    float val = 0.f;
    if (c < 32) {
        int i = n >> 8, j = n & 255;
        float r = (float)(((c & 1) ? j : i) - 128) * (float)(3.14159265358979323846 / 256.0);
        float s = exp2f(0.5f * (float)(c >> 1));
        val = sinf(r * s);
    }
    cat[(size_t)n * 1088 + c] = __float2bfloat16(val);
}

// ---------------------------------------------------------------------------
// Grouped 3x3 conv + leaky_relu, tap-hoisted: per-thread tap validity/offsets
// computed ONCE outside the input-channel loop.
// ---------------------------------------------------------------------------
__global__ void conv3x3_kernel(const float* __restrict__ in, const float* __restrict__ w,
                               const float* __restrict__ bias, float* __restrict__ out,
                               int Cin, int Cout, int Hin, int Win,
                               int Hout, int Wout, int pad, int groups) {
    int oc = blockIdx.x;
    int icpg = Cin / groups;
    int ocpg = Cout / groups;
    int grp = oc / ocpg;
    extern __shared__ float sm[];
    float* sw  = sm;
    float* red = sm + icpg * 9;
    for (int i = threadIdx.x; i < icpg * 9; i += blockDim.x)
        sw[i] = w[(size_t)oc * icpg * 9 + i];
    __syncthreads();

    int icq = threadIdx.x >> 6;
    int px  = threadIdx.x & 63;
    float acc = 0.f;
    if (px < Hout * Wout) {
        int oy = px / Wout, ox = px % Wout;
        int  toff[9];
        bool tval[9];
        #pragma unroll
        for (int t = 0; t < 9; t++) {
            int ky = t / 3, kx = t % 3;
            int iy = oy + ky - pad, ix = ox + kx - pad;
            tval[t] = (iy >= 0) & (iy < Hin) & (ix >= 0) & (ix < Win);
            toff[t] = tval[t] ? iy * Win + ix : 0;
        }
        const float* inb = in + (size_t)grp * icpg * Hin * Win;
        int HW = Hin * Win;
        for (int ic = icq; ic < icpg; ic += 4) {
            const float* ip = inb + (size_t)ic * HW;
            const float* wp = sw + ic * 9;
            #pragma unroll
            for (int t = 0; t < 9; t++)
                if (tval[t]) acc = fmaf(ip[toff[t]], wp[t], acc);
        }
    }
    red[icq * 64 + px] = acc;
    __syncthreads();
    if (icq == 0 && px < Hout * Wout) {
        float v = bias[oc] + red[px] + red[64 + px] + red[128 + px] + red[192 + px];
        out[(size_t)oc * Hout * Wout + px] = v > 0.f ? v : 0.01f * v;
    }
}

__global__ void wnorm_kernel(const float* __restrict__ v, const float* __restrict__ g,
                             __nv_bfloat16* __restrict__ w, int K) {
    int row = blockIdx.x;
    const float* vr = v + (size_t)row * K;
    float s = 0.f;
    for (int k = threadIdx.x; k < K; k += blockDim.x) { float x = vr[k]; s = fmaf(x, x, s); }
    __shared__ float red[128];
    red[threadIdx.x] = s;
    __syncthreads();
    for (int o = 64; o; o >>= 1) {
        if (threadIdx.x < o) red[threadIdx.x] += red[threadIdx.x + o];
        __syncthreads();
    }
    float scale = g[row] / sqrtf(red[0]);
    for (int k = threadIdx.x; k < K; k += blockDim.x)
        w[(size_t)row * K + k] = __float2bfloat16(vr[k] * scale);
}

__global__ void conv_w1g_kernel(const float* __restrict__ w1, __nv_bfloat16* __restrict__ o) {
    int idx = blockIdx.x * blockDim.x + threadIdx.x;   // 1024*64
    int j = idx >> 6, k = idx & 63;
    o[idx] = __float2bfloat16(k < 32 ? w1[(size_t)j * 2080 + k] : 0.f);
}
__global__ void conv_w2cat_kernel(const float* __restrict__ w2, __nv_bfloat16* __restrict__ o) {
    int idx = blockIdx.x * blockDim.x + threadIdx.x;   // 512*1088
    int j = idx / 1088, r = idx % 1088;
    float v;
    if (r < 32)       v = w2[(size_t)j * 1056 + r];
    else if (r < 64)  v = 0.f;
    else              v = w2[(size_t)j * 1056 + 32 + (r - 64)];
    o[idx] = __float2bfloat16(v);
}

__global__ void bias1_kernel(const float* __restrict__ feat, const float* __restrict__ w1,
                             const float* __restrict__ b1, float* __restrict__ out) {
    int j = blockIdx.x * 8 + (threadIdx.x >> 5);
    int lane = threadIdx.x & 31;
    const float* wr = w1 + (size_t)j * 2080 + 32;
    float s = 0.f;
    for (int k = lane; k < 2048; k += 32) s = fmaf(feat[k], wr[k], s);
    #pragma unroll
    for (int o = 16; o; o >>= 1) s += __shfl_down_sync(0xffffffffu, s, o);
    if (lane == 0) out[j] = b1[j] + s;
}

__global__ void head_kernel(const float* __restrict__ h2, const float* __restrict__ w3,
                            const float* __restrict__ b3, float* __restrict__ out) {
    __shared__ float sw[1536];
    for (int i = threadIdx.x; i < 1536; i += blockDim.x) sw[i] = w3[i];
    __syncthreads();
    int n = (blockIdx.x * blockDim.x + threadIdx.x) >> 5;
    int lane = threadIdx.x & 31;
    const float* hr = h2 + (size_t)n * 512;
    float d0 = 0.f, d1 = 0.f, d2 = 0.f;
    for (int t = lane; t < 512; t += 32) {
        float x = hr[t];
        d0 = fmaf(x, sw[t], d0);
        d1 = fmaf(x, sw[512 + t], d1);
        d2 = fmaf(x, sw[1024 + t], d2);
    }
    #pragma unroll
    for (int o = 16; o; o >>= 1) {
        d0 += __shfl_down_sync(0xffffffffu, d0, o);
        d1 += __shfl_down_sync(0xffffffffu, d1, o);
        d2 += __shfl_down_sync(0xffffffffu, d2, o);
    }
    if (lane == 0) {
        out[n]          = 1.1f / (1.f + expf(-(d0 + b3[0]))) - 0.05f;
        out[65536 + n]  = 1.1f / (1.f + expf(-(d1 + b3[1]))) - 0.05f;
        out[131072 + n] = 1.1f / (1.f + expf(-(d2 + b3[2]))) - 0.05f;
    }
}

// ---------------------------------------------------------------------------
// bf16 GEMM: mma.sync.m16n8k16 + ldmatrix + cp.async.
// 128x128 CTA tile, 4 warps (2x2), warp tile 64x64, BK=64, 3 stages (96KB),
// 128 threads, __launch_bounds__(128,2) -> guaranteed 2 CTAs/SM.
// C fp32 (+ optional bf16 shadow, own stride).
// ---------------------------------------------------------------------------
enum { EP_LRELU_BIAS = 1, EP_RES_OUT = 3 };

#define BM 128
#define BN 128
#define BKB 64
#define STAGES 3
#define OPB (BM * BKB * 2)        // 16 KB
#define STB (2 * OPB)             // 32 KB
#define GSMEM (STAGES * STB)      // 96 KB

__device__ __forceinline__ uint32_t smem_u32(const void* p) {
    uint32_t a;
    asm("{ .reg .u64 t; cvta.to.shared.u64 t, %1; cvt.u32.u64 %0, t; }" : "=r"(a) : "l"(p));
    return a;
}
__device__ __forceinline__ void cp_async16(uint32_t sa, const __nv_bfloat16* g) {
    asm volatile("cp.async.cg.shared.global [%0], [%1], 16;" :: "r"(sa), "l"(g));
}
__device__ __forceinline__ void ldsm4(uint32_t* r, uint32_t addr) {
    asm volatile("ldmatrix.sync.aligned.m8n8.x4.shared.b16 {%0,%1,%2,%3}, [%4];"
                 : "=r"(r[0]), "=r"(r[1]), "=r"(r[2]), "=r"(r[3]) : "r"(addr));
}
__device__ __forceinline__ void mma_bf16(float* c, const uint32_t* a, const uint32_t* b) {
    asm volatile(
        "mma.sync.aligned.m16n8k16.row.col.f32.bf16.bf16.f32 "
        "{%0,%1,%2,%3}, {%4,%5,%6,%7}, {%8,%9}, {%0,%1,%2,%3};"
        : "+f"(c[0]), "+f"(c[1]), "+f"(c[2]), "+f"(c[3])
        : "r"(a[0]), "r"(a[1]), "r"(a[2]), "r"(a[3]), "r"(b[0]), "r"(b[1]));
}
__device__ __forceinline__ uint32_t pack_bf16x2(float lo, float hi) {
    uint32_t u;
    asm("cvt.rn.bf16x2.f32 %0, %1, %2;" : "=r"(u) : "f"(hi), "f"(lo));
    return u;
}

template <int EP, int WBF>
__global__ __launch_bounds__(128, 2)
void gemm_bf(const __nv_bfloat16* __restrict__ A, int lda,
             const __nv_bfloat16* __restrict__ B, int ldb,
             float* __restrict__ C, int ldc,
             __nv_bfloat16* __restrict__ Cbf, int ldcbf,
             const float* __restrict__ Res, int ldres,
             const float* __restrict__ bias, int K) {
    extern __shared__ char smem[];
    uint32_t sbase = smem_u32(smem);

    int tid = threadIdx.x;
    int wid = tid >> 5, lane = tid & 31;
    int g = lane >> 2, tg = lane & 3;
    int wm = (wid >> 1) * 64;
    int wn = (wid & 1) * 64;

    long brow = blockIdx.y, bcol = blockIdx.x;
    const __nv_bfloat16* Ab = A + brow * BM * (long)lda;
    const __nv_bfloat16* Bb = B + bcol * BN * (long)ldb;
    C   += brow * BM * (long)ldc   + bcol * BN;
    if (WBF) Cbf += brow * BM * (long)ldcbf + bcol * BN;
    Res += brow * BM * (long)ldres + bcol * BN;
    const float* biasp = bias + bcol * BN;

    // ldmatrix address components (byte offsets within 128-row x 128B tile)
    uint32_t aRow[4], aXor[4], bRow[4], bXor[4];
    uint32_t akb = (lane >> 4) * 16;
    uint32_t bkb = ((lane >> 3) & 1) * 16;
    #pragma unroll
    for (int s = 0; s < 4; s++) {
        uint32_t r = wm + s * 16 + (lane & 15);
        aRow[s] = r * 128;
        aXor[s] = (r & 7) << 4;
    }
    #pragma unroll
    for (int p = 0; p < 4; p++) {
        uint32_t r = wn + p * 16 + ((lane >> 4) << 3) + (lane & 7);
        bRow[p] = r * 128;
        bXor[p] = (r & 7) << 4;
    }

    float acc[4][8][4];
    #pragma unroll
    for (int s = 0; s < 4; s++)
        #pragma unroll
        for (int nt = 0; nt < 8; nt++)
            #pragma unroll
            for (int q = 0; q < 4; q++) acc[s][nt][q] = 0.f;

    int T = K / BKB;

    // loader: 1024 16B-chunks per operand tile, 8 per thread per operand
    auto load_stage = [&](int u, int st) {
        const __nv_bfloat16* Ag = Ab + u * BKB;
        const __nv_bfloat16* Bg = Bb + u * BKB;
        uint32_t sA = sbase + st * STB;
        uint32_t sB = sA + OPB;
        #pragma unroll
        for (int j = 0; j < 8; j++) {
            int idx = tid + 128 * j;
            int r = idx >> 3, c = idx & 7;
            uint32_t sw = r * 128 + ((c * 16) ^ ((r & 7) << 4));
            cp_async16(sA + sw, Ag + (long)r * lda + c * 8);
            cp_async16(sB + sw, Bg + (long)r * ldb + c * 8);
        }
    };

    #pragma unroll
    for (int p = 0; p < STAGES - 1; p++) {
        if (p < T) load_stage(p, p);
        asm volatile("cp.async.commit_group;");
    }

    for (int t = 0; t < T; t++) {
        asm volatile("cp.async.wait_group %0;" :: "n"(STAGES - 2));
        __syncthreads();
        int u = t + STAGES - 1;
        if (u < T) load_stage(u, u % STAGES);
        asm volatile("cp.async.commit_group;");

        uint32_t sA = sbase + (t % STAGES) * STB;
        uint32_t sB = sA + OPB;
        #pragma unroll
        for (int kk = 0; kk < 4; kk++) {
            uint32_t af[4][4], bp[4][4];
            #pragma unroll
            for (int s = 0; s < 4; s++)
                ldsm4(af[s], sA + aRow[s] + (((kk * 32) + akb) ^ aXor[s]));
            #pragma unroll
            for (int p = 0; p < 4; p++)
                ldsm4(bp[p], sB + bRow[p] + (((kk * 32) + bkb) ^ bXor[p]));
            #pragma unroll
            for (int s = 0; s < 4; s++)
                #pragma unroll
                for (int p = 0; p < 4; p++) {
                    mma_bf16(acc[s][p * 2 + 0], af[s], &bp[p][0]);
                    mma_bf16(acc[s][p * 2 + 1], af[s], &bp[p][2]);
                }
        }
    }

    // epilogue
    #pragma unroll
    for (int s = 0; s < 4; s++) {
        #pragma unroll
        for (int half = 0; half < 2; half++) {
            long row = wm + s * 16 + g + half * 8;
            #pragma unroll
            for (int nt = 0; nt < 8; nt++) {
                int col = wn + nt * 8 + tg * 2;
                float v0 = acc[s][nt][half * 2 + 0];
                float v1 = acc[s][nt][half * 2 + 1];
                if (EP == EP_LRELU_BIAS) {
                    v0 += biasp[col]; v1 += biasp[col + 1];
                    v0 = v0 > 0.f ? v0 : 0.01f * v0;
                    v1 = v1 > 0.f ? v1 : 0.01f * v1;
                } else {  // EP_RES_OUT
                    v0 += biasp[col]; v1 += biasp[col + 1];
                    v0 = v0 > 0.f ? v0 : 0.01f * v0;
                    v1 = v1 > 0.f ? v1 : 0.01f * v1;
                    float2 r = *reinterpret_cast<const float2*>(Res + row * ldres + col);
                    v0 += r.x; v1 += r.y;
                }
                float2 o; o.x = v0; o.y = v1;
                *reinterpret_cast<float2*>(C + row * ldc + col) = o;
                if (WBF)
                    *reinterpret_cast<uint32_t*>(Cbf + row * ldcbf + col) = pack_bf16x2(v0, v1);
            }
        }
    }
}

static void launch_gemm(int ep, const __nv_bfloat16* A, int lda,
                        const __nv_bfloat16* B, int ldb,
                        float* C, int ldc, __nv_bfloat16* Cbf, int ldcbf,
                        const float* Res, int ldres,
                        const float* bias, int M, int N, int K) {
    dim3 grd(N / BN, M / BM);
    if (ep == EP_LRELU_BIAS) {
        if (Cbf) {
            cudaFuncSetAttribute(gemm_bf<EP_LRELU_BIAS, 1>, cudaFuncAttributeMaxDynamicSharedMemorySize, GSMEM);
            gemm_bf<EP_LRELU_BIAS, 1><<<grd, 128, GSMEM>>>(A, lda, B, ldb, C, ldc, Cbf, ldcbf, Res, ldres, bias, K);
        } else {
            cudaFuncSetAttribute(gemm_bf<EP_LRELU_BIAS, 0>, cudaFuncAttributeMaxDynamicSharedMemorySize, GSMEM);
            gemm_bf<EP_LRELU_BIAS, 0><<<grd, 128, GSMEM>>>(A, lda, B, ldb, C, ldc, Cbf, ldcbf, Res, ldres, bias, K);
        }
    } else {
        cudaFuncSetAttribute(gemm_bf<EP_RES_OUT, 1>, cudaFuncAttributeMaxDynamicSharedMemorySize, GSMEM);
        gemm_bf<EP_RES_OUT, 1><<<grd, 128, GSMEM>>>(A, lda, B, ldb, C, ldc, Cbf, ldcbf, Res, ldres, bias, K);
    }
}

// ---------------------------------------------------------------------------
// kernel_launch
// ---------------------------------------------------------------------------
extern "C" void kernel_launch(void* const* d_in, const int* in_sizes, int n_in,
                              void* d_out, int out_size) {
    const float* feature = (const float*)d_in[0];
    const float* cw1 = (const float*)d_in[1];  const float* cb1 = (const float*)d_in[2];
    const float* cw2 = (const float*)d_in[3];  const float* cb2 = (const float*)d_in[4];
    const float* cw3 = (const float*)d_in[5];  const float* cb3 = (const float*)d_in[6];
    const float* cw4 = (const float*)d_in[7];  const float* cb4 = (const float*)d_in[8];
    const float* cw5 = (const float*)d_in[9];  const float* cb5 = (const float*)d_in[10];
    const float* w1  = (const float*)d_in[11]; const float* b1  = (const float*)d_in[12];
    const float* m1_vf = (const float*)d_in[13]; const float* m1_gf = (const float*)d_in[14];
    const float* m1_bf = (const float*)d_in[15]; const float* m1_vg = (const float*)d_in[16];
    const float* m1_gg = (const float*)d_in[17]; const float* m1_bg = (const float*)d_in[18];
    const float* w2  = (const float*)d_in[19]; const float* b2  = (const float*)d_in[20];
    const float* m2_vf = (const float*)d_in[21]; const float* m2_gf = (const float*)d_in[22];
    const float* m2_bf = (const float*)d_in[23]; const float* m2_vg = (const float*)d_in[24];
    const float* m2_gg = (const float*)d_in[25]; const float* m2_bg = (const float*)d_in[26];
    const float* w3  = (const float*)d_in[27]; const float* b3  = (const float*)d_in[28];
    float* out = (float*)d_out;

    __nv_bfloat16 *cat, *h2_bf, *wm1F, *wm1G, *wm2F, *wm2G, *w1g, *w2c;
    float *mid, *h2, *conv0, *conv1, *feat, *bias1;
    cudaGetSymbolAddress((void**)&cat,   g_cat);
    cudaGetSymbolAddress((void**)&mid,   g_mid);
    cudaGetSymbolAddress((void**)&h2,    g_h2);
    cudaGetSymbolAddress((void**)&h2_bf, g_h2_bf);
    cudaGetSymbolAddress((void**)&wm1F,  g_wm1F);
    cudaGetSymbolAddress((void**)&wm1G,  g_wm1G);
    cudaGetSymbolAddress((void**)&wm2F,  g_wm2F);
    cudaGetSymbolAddress((void**)&wm2G,  g_wm2G);
    cudaGetSymbolAddress((void**)&w1g,   g_w1g_bf);
    cudaGetSymbolAddress((void**)&w2c,   g_w2cat);
    cudaGetSymbolAddress((void**)&conv0, g_conv0);
    cudaGetSymbolAddress((void**)&conv1, g_conv1);
    cudaGetSymbolAddress((void**)&feat,  g_feat);
    cudaGetSymbolAddress((void**)&bias1, g_bias1);

    // --- positional grid features into cat[:, 0:64] ---
    grid_kernel<<<(NPIX * 64) / 256, 256>>>(cat);

    // --- conv stack ---
    conv3x3_kernel<<<768, 256, (448 * 9 + 256) * 4>>>(feature, cw1, cb1, conv0, 1792, 768, 8, 8, 8, 8, 1, 4);
    conv3x3_kernel<<<768, 256, (256 * 9 + 256) * 4>>>(conv0, cw2, cb2, conv1, 768, 768, 8, 8, 8, 8, 1, 3);
    conv3x3_kernel<<<768, 256, (384 * 9 + 256) * 4>>>(conv1, cw3, cb3, conv0, 768, 768, 8, 8, 8, 8, 1, 2);
    conv3x3_kernel<<<768, 256, (256 * 9 + 256) * 4>>>(conv0, cw4, cb4, conv1, 768, 768, 8, 8, 6, 6, 0, 3);
    conv3x3_kernel<<<128, 256, (768 * 9 + 256) * 4>>>(conv1, cw5, cb5, feat, 768, 128, 6, 6, 4, 4, 0, 1);

    // --- fold feat @ w1[:,32:].T + b1 into a bias vector ---
    bias1_kernel<<<128, 256>>>(feat, w1, b1, bias1);

    // --- weight prep (bf16) ---
    wnorm_kernel<<<8 * 512, 128>>>(m1_vf, m1_gf, wm1F, 512);
    wnorm_kernel<<<8 * 512, 128>>>(m1_vg, m1_gg, wm1G, 512);
    wnorm_kernel<<<8 * 256, 128>>>(m2_vf, m2_gf, wm2F, 256);
    wnorm_kernel<<<8 * 256, 128>>>(m2_vg, m2_gg, wm2G, 256);
    conv_w1g_kernel<<<(1024 * 64) / 256, 256>>>(w1, w1g);
    conv_w2cat_kernel<<<(512 * 1088) / 256, 256>>>(w2, w2c);

    // --- mid = lrelu(grid @ w1grid.T + bias1): A = cat[:,0:64] ---
    launch_gemm(EP_LRELU_BIAS, cat, 1088, w1g, 64, mid, 1024, cat + 64, 1088,
                mid, 1024, bias1, NPIX, 1024, 64);

    // --- mem stack 1: halves of 1024 inside cat[:,64:1088] + fp32 mid ---
    for (int s = 0; s < 8; s++) {
        launch_gemm(EP_RES_OUT, cat + 64 + 512, 1088, wm1F + (size_t)s * 512 * 512, 512,
                    mid, 1024, cat + 64, 1088, mid, 1024, m1_bf + s * 512, NPIX, 512, 512);
        launch_gemm(EP_RES_OUT, cat + 64, 1088, wm1G + (size_t)s * 512 * 512, 512,
                    mid + 512, 1024, cat + 64 + 512, 1088, mid + 512, 1024, m1_bg + s * 512, NPIX, 512, 512);
    }

    // --- h2 = lrelu(cat @ w2cat.T + b2): single K=1088 GEMM ---
    launch_gemm(EP_LRELU_BIAS, cat, 1088, w2c, 1088, h2, 512, h2_bf, 512,
                h2, 512, b2, NPIX, 512, 1088);

    // --- mem stack 2: halves of 512 (256 each) ---
    for (int s = 0; s < 8; s++) {
        launch_gemm(EP_RES_OUT, h2_bf + 256, 512, wm2F + (size_t)s * 256 * 256, 256,
                    h2, 512, h2_bf, 512, h2, 512, m2_bf + s * 256, NPIX, 256, 256);
        launch_gemm(EP_RES_OUT, h2_bf, 512, wm2G + (size_t)s * 256 * 256, 256,
                    h2 + 256, 512, h2_bf + 256, 512, h2 + 256, 512, m2_bg + s * 256, NPIX, 256, 256);
    }

    // --- head ---
    head_kernel<<<NPIX / 8, 256>>>(h2, w3, b3, out);
}

// round 9
// speedup vs baseline: 5.4532x; 1.0412x over previous
#include <cuda_runtime.h>
#include <cuda_bf16.h>
#include <cstdint>
#include <math.h>

// ---------------------------------------------------------------------------
// Scratch
// ---------------------------------------------------------------------------
#define NPIX 65536
// concatenated bf16 activations: [grid(64, zero-padded) | mid(1024)]
__device__ __nv_bfloat16 g_cat[NPIX * 1088];
__device__ float         g_mid [NPIX * 1024];         // fp32 residual path
__device__ float         g_h2  [NPIX * 512];
__device__ __nv_bfloat16 g_h2_bf[NPIX * 512];
__device__ __nv_bfloat16 g_wm1F[8 * 512 * 512];
__device__ __nv_bfloat16 g_wm1G[8 * 512 * 512];
__device__ __nv_bfloat16 g_wm2F[8 * 256 * 256];
__device__ __nv_bfloat16 g_wm2G[8 * 256 * 256];
__device__ __nv_bfloat16 g_w1g_bf[1024 * 64];         // w1[:, :32] zero-padded
__device__ __nv_bfloat16 g_w2cat[512 * 1088];         // [w2grid(64pad) | w2mid(1024)]
__device__ float g_conv0[768 * 8 * 8];
__device__ float g_conv1[768 * 8 * 8];
__device__ float g_feat[2048];
__device__ float g_bias1[1024];

// ---------------------------------------------------------------------------
// Grid features -> bf16 into g_cat cols [0,64), stride 1088
// ---------------------------------------------------------------------------
__global__ void grid_kernel(__nv_bfloat16* __restrict__ cat) {
    int idx = blockIdx.x * blockDim.x + threadIdx.x;      // n*64 + c
    int n = idx >> 6, c = idx & 63;
    float val = 0.f;
    if (c < 32) {
        int i = n >> 8, j = n & 255;
        float r = (float)(((c & 1) ? j : i) - 128) * (float)(3.14159265358979323846 / 256.0);
        float s = exp2f(0.5f * (float)(c >> 1));
        val = sinf(r * s);
    }
    cat[(size_t)n * 1088 + c] = __float2bfloat16(val);
}

// ---------------------------------------------------------------------------
// Grouped 3x3 conv + leaky_relu. One block per output channel, 512 threads:
// 8-way input-channel split (latency hiding), R7-style inner loop.
// ---------------------------------------------------------------------------
__global__ void conv3x3_kernel(const float* __restrict__ in, const float* __restrict__ w,
                               const float* __restrict__ bias, float* __restrict__ out,
                               int Cin, int Cout, int Hin, int Win,
                               int Hout, int Wout, int pad, int groups) {
    int oc = blockIdx.x;
    int icpg = Cin / groups;
    int ocpg = Cout / groups;
    int grp = oc / ocpg;
    extern __shared__ float sm[];
    float* sw  = sm;                 // icpg*9
    float* red = sm + icpg * 9;      // 8*64
    for (int i = threadIdx.x; i < icpg * 9; i += blockDim.x)
        sw[i] = w[(size_t)oc * icpg * 9 + i];
    __syncthreads();

    int icq = threadIdx.x >> 6;      // 0..7
    int px  = threadIdx.x & 63;
    float acc = 0.f;
    if (px < Hout * Wout) {
        int oy = px / Wout, ox = px % Wout;
        const float* inb = in + (size_t)grp * icpg * Hin * Win;
        for (int ic = icq; ic < icpg; ic += 8) {
            const float* ip = inb + (size_t)ic * Hin * Win;
            const float* wp = sw + ic * 9;
            #pragma unroll
            for (int ky = 0; ky < 3; ky++) {
                int iy = oy + ky - pad;
                if (iy < 0 || iy >= Hin) continue;
                #pragma unroll
                for (int kx = 0; kx < 3; kx++) {
                    int ix = ox + kx - pad;
                    if (ix < 0 || ix >= Win) continue;
                    acc = fmaf(ip[iy * Win + ix], wp[ky * 3 + kx], acc);
                }
            }
        }
    }
    red[icq * 64 + px] = acc;
    __syncthreads();
    if (icq == 0 && px < Hout * Wout) {
        float v = bias[oc];
        #pragma unroll
        for (int q = 0; q < 8; q++) v += red[q * 64 + px];
        out[(size_t)oc * Hout * Wout + px] = v > 0.f ? v : 0.01f * v;
    }
}

__global__ void wnorm_kernel(const float* __restrict__ v, const float* __restrict__ g,
                             __nv_bfloat16* __restrict__ w, int K) {
    int row = blockIdx.x;
    const float* vr = v + (size_t)row * K;
    float s = 0.f;
    for (int k = threadIdx.x; k < K; k += blockDim.x) { float x = vr[k]; s = fmaf(x, x, s); }
    __shared__ float red[128];
    red[threadIdx.x] = s;
    __syncthreads();
    for (int o = 64; o; o >>= 1) {
        if (threadIdx.x < o) red[threadIdx.x] += red[threadIdx.x + o];
        __syncthreads();
    }
    float scale = g[row] / sqrtf(red[0]);
    for (int k = threadIdx.x; k < K; k += blockDim.x)
        w[(size_t)row * K + k] = __float2bfloat16(vr[k] * scale);
}

__global__ void conv_w1g_kernel(const float* __restrict__ w1, __nv_bfloat16* __restrict__ o) {
    int idx = blockIdx.x * blockDim.x + threadIdx.x;   // 1024*64
    int j = idx >> 6, k = idx & 63;
    o[idx] = __float2bfloat16(k < 32 ? w1[(size_t)j * 2080 + k] : 0.f);
}
__global__ void conv_w2cat_kernel(const float* __restrict__ w2, __nv_bfloat16* __restrict__ o) {
    int idx = blockIdx.x * blockDim.x + threadIdx.x;   // 512*1088
    int j = idx / 1088, r = idx % 1088;
    float v;
    if (r < 32)       v = w2[(size_t)j * 1056 + r];
    else if (r < 64)  v = 0.f;
    else              v = w2[(size_t)j * 1056 + 32 + (r - 64)];
    o[idx] = __float2bfloat16(v);
}

__global__ void bias1_kernel(const float* __restrict__ feat, const float* __restrict__ w1,
                             const float* __restrict__ b1, float* __restrict__ out) {
    int j = blockIdx.x * 8 + (threadIdx.x >> 5);
    int lane = threadIdx.x & 31;
    const float* wr = w1 + (size_t)j * 2080 + 32;
    float s = 0.f;
    for (int k = lane; k < 2048; k += 32) s = fmaf(feat[k], wr[k], s);
    #pragma unroll
    for (int o = 16; o; o >>= 1) s += __shfl_down_sync(0xffffffffu, s, o);
    if (lane == 0) out[j] = b1[j] + s;
}

__global__ void head_kernel(const float* __restrict__ h2, const float* __restrict__ w3,
                            const float* __restrict__ b3, float* __restrict__ out) {
    __shared__ float sw[1536];
    for (int i = threadIdx.x; i < 1536; i += blockDim.x) sw[i] = w3[i];
    __syncthreads();
    int n = (blockIdx.x * blockDim.x + threadIdx.x) >> 5;
    int lane = threadIdx.x & 31;
    const float* hr = h2 + (size_t)n * 512;
    float d0 = 0.f, d1 = 0.f, d2 = 0.f;
    for (int t = lane; t < 512; t += 32) {
        float x = hr[t];
        d0 = fmaf(x, sw[t], d0);
        d1 = fmaf(x, sw[512 + t], d1);
        d2 = fmaf(x, sw[1024 + t], d2);
    }
    #pragma unroll
    for (int o = 16; o; o >>= 1) {
        d0 += __shfl_down_sync(0xffffffffu, d0, o);
        d1 += __shfl_down_sync(0xffffffffu, d1, o);
        d2 += __shfl_down_sync(0xffffffffu, d2, o);
    }
    if (lane == 0) {
        out[n]          = 1.1f / (1.f + expf(-(d0 + b3[0]))) - 0.05f;
        out[65536 + n]  = 1.1f / (1.f + expf(-(d1 + b3[1]))) - 0.05f;
        out[131072 + n] = 1.1f / (1.f + expf(-(d2 + b3[2]))) - 0.05f;
    }
}

// ---------------------------------------------------------------------------
// bf16 GEMM: mma.sync.m16n8k16 + ldmatrix + cp.async.
// 128x128 CTA tile, 4 warps (2x2), warp tile 64x64, BK=64, 3 stages (96KB),
// 128 threads, __launch_bounds__(128,2) -> 2 CTAs/SM.
// Fragment double-buffering: kk+1 LDSMs issue under kk's MMAs.
// ---------------------------------------------------------------------------
enum { EP_LRELU_BIAS = 1, EP_RES_OUT = 3 };

#define BM 128
#define BN 128
#define BKB 64
#define STAGES 3
#define OPB (BM * BKB * 2)        // 16 KB
#define STB (2 * OPB)             // 32 KB
#define GSMEM (STAGES * STB)      // 96 KB

__device__ __forceinline__ uint32_t smem_u32(const void* p) {
    uint32_t a;
    asm("{ .reg .u64 t; cvta.to.shared.u64 t, %1; cvt.u32.u64 %0, t; }" : "=r"(a) : "l"(p));
    return a;
}
__device__ __forceinline__ void cp_async16(uint32_t sa, const __nv_bfloat16* g) {
    asm volatile("cp.async.cg.shared.global [%0], [%1], 16;" :: "r"(sa), "l"(g));
}
__device__ __forceinline__ void ldsm4(uint32_t* r, uint32_t addr) {
    asm volatile("ldmatrix.sync.aligned.m8n8.x4.shared.b16 {%0,%1,%2,%3}, [%4];"
                 : "=r"(r[0]), "=r"(r[1]), "=r"(r[2]), "=r"(r[3]) : "r"(addr));
}
__device__ __forceinline__ void mma_bf16(float* c, const uint32_t* a, const uint32_t* b) {
    asm volatile(
        "mma.sync.aligned.m16n8k16.row.col.f32.bf16.bf16.f32 "
        "{%0,%1,%2,%3}, {%4,%5,%6,%7}, {%8,%9}, {%0,%1,%2,%3};"
        : "+f"(c[0]), "+f"(c[1]), "+f"(c[2]), "+f"(c[3])
        : "r"(a[0]), "r"(a[1]), "r"(a[2]), "r"(a[3]), "r"(b[0]), "r"(b[1]));
}
__device__ __forceinline__ uint32_t pack_bf16x2(float lo, float hi) {
    uint32_t u;
    asm("cvt.rn.bf16x2.f32 %0, %1, %2;" : "=r"(u) : "f"(hi), "f"(lo));
    return u;
}

template <int EP, int WBF>
__global__ __launch_bounds__(128, 2)
void gemm_bf(const __nv_bfloat16* __restrict__ A, int lda,
             const __nv_bfloat16* __restrict__ B, int ldb,
             float* __restrict__ C, int ldc,
             __nv_bfloat16* __restrict__ Cbf, int ldcbf,
             const float* __restrict__ Res, int ldres,
             const float* __restrict__ bias, int K) {
    extern __shared__ char smem[];
    uint32_t sbase = smem_u32(smem);

    int tid = threadIdx.x;
    int wid = tid >> 5, lane = tid & 31;
    int g = lane >> 2, tg = lane & 3;
    int wm = (wid >> 1) * 64;
    int wn = (wid & 1) * 64;

    long brow = blockIdx.y, bcol = blockIdx.x;
    const __nv_bfloat16* Ab = A + brow * BM * (long)lda;
    const __nv_bfloat16* Bb = B + bcol * BN * (long)ldb;
    C   += brow * BM * (long)ldc   + bcol * BN;
    if (WBF) Cbf += brow * BM * (long)ldcbf + bcol * BN;
    Res += brow * BM * (long)ldres + bcol * BN;
    const float* biasp = bias + bcol * BN;

    // ldmatrix address components (byte offsets within 128-row x 128B tile)
    uint32_t aRow[4], aXor[4], bRow[4], bXor[4];
    uint32_t akb = (lane >> 4) * 16;
    uint32_t bkb = ((lane >> 3) & 1) * 16;
    #pragma unroll
    for (int s = 0; s < 4; s++) {
        uint32_t r = wm + s * 16 + (lane & 15);
        aRow[s] = r * 128;
        aXor[s] = (r & 7) << 4;
    }
    #pragma unroll
    for (int p = 0; p < 4; p++) {
        uint32_t r = wn + p * 16 + ((lane >> 4) << 3) + (lane & 7);
        bRow[p] = r * 128;
        bXor[p] = (r & 7) << 4;
    }

    float acc[4][8][4];
    #pragma unroll
    for (int s = 0; s < 4; s++)
        #pragma unroll
        for (int nt = 0; nt < 8; nt++)
            #pragma unroll
            for (int q = 0; q < 4; q++) acc[s][nt][q] = 0.f;

    int T = K / BKB;

    // loader: 1024 16B-chunks per operand tile, 8 per thread per operand
    auto load_stage = [&](int u, int st) {
        const __nv_bfloat16* Ag = Ab + u * BKB;
        const __nv_bfloat16* Bg = Bb + u * BKB;
        uint32_t sA = sbase + st * STB;
        uint32_t sB = sA + OPB;
        #pragma unroll
        for (int j = 0; j < 8; j++) {
            int idx = tid + 128 * j;
            int r = idx >> 3, c = idx & 7;
            uint32_t sw = r * 128 + ((c * 16) ^ ((r & 7) << 4));
            cp_async16(sA + sw, Ag + (long)r * lda + c * 8);
            cp_async16(sB + sw, Bg + (long)r * ldb + c * 8);
        }
    };

    // fragment loader for one kk slice
    auto load_frags = [&](uint32_t sA, uint32_t sB, int kk,
                          uint32_t af[4][4], uint32_t bp[4][4]) {
        #pragma unroll
        for (int s = 0; s < 4; s++)
            ldsm4(af[s], sA + aRow[s] + (((kk * 32) + akb) ^ aXor[s]));
        #pragma unroll
        for (int p = 0; p < 4; p++)
            ldsm4(bp[p], sB + bRow[p] + (((kk * 32) + bkb) ^ bXor[p]));
    };

    #pragma unroll
    for (int p = 0; p < STAGES - 1; p++) {
        if (p < T) load_stage(p, p);
        asm volatile("cp.async.commit_group;");
    }

    uint32_t af[2][4][4], bp[2][4][4];

    for (int t = 0; t < T; t++) {
        asm volatile("cp.async.wait_group %0;" :: "n"(STAGES - 2));
        __syncthreads();
        int u = t + STAGES - 1;
        if (u < T) load_stage(u, u % STAGES);
        asm volatile("cp.async.commit_group;");

        uint32_t sA = sbase + (t % STAGES) * STB;
        uint32_t sB = sA + OPB;

        load_frags(sA, sB, 0, af[0], bp[0]);
        #pragma unroll
        for (int kk = 0; kk < 4; kk++) {
            int cur = kk & 1, nxt = cur ^ 1;
            if (kk < 3) load_frags(sA, sB, kk + 1, af[nxt], bp[nxt]);
            #pragma unroll
            for (int s = 0; s < 4; s++)
                #pragma unroll
                for (int p = 0; p < 4; p++) {
                    mma_bf16(acc[s][p * 2 + 0], af[cur][s], &bp[cur][p][0]);
                    mma_bf16(acc[s][p * 2 + 1], af[cur][s], &bp[cur][p][2]);
                }
        }
    }

    // epilogue
    #pragma unroll
    for (int s = 0; s < 4; s++) {
        #pragma unroll
        for (int half = 0; half < 2; half++) {
            long row = wm + s * 16 + g + half * 8;
            #pragma unroll
            for (int nt = 0; nt < 8; nt++) {
                int col = wn + nt * 8 + tg * 2;
                float v0 = acc[s][nt][half * 2 + 0];
                float v1 = acc[s][nt][half * 2 + 1];
                if (EP == EP_LRELU_BIAS) {
                    v0 += biasp[col]; v1 += biasp[col + 1];
                    v0 = v0 > 0.f ? v0 : 0.01f * v0;
                    v1 = v1 > 0.f ? v1 : 0.01f * v1;
                } else {  // EP_RES_OUT
                    v0 += biasp[col]; v1 += biasp[col + 1];
                    v0 = v0 > 0.f ? v0 : 0.01f * v0;
                    v1 = v1 > 0.f ? v1 : 0.01f * v1;
                    float2 r = *reinterpret_cast<const float2*>(Res + row * ldres + col);
                    v0 += r.x; v1 += r.y;
                }
                float2 o; o.x = v0; o.y = v1;
                *reinterpret_cast<float2*>(C + row * ldc + col) = o;
                if (WBF)
                    *reinterpret_cast<uint32_t*>(Cbf + row * ldcbf + col) = pack_bf16x2(v0, v1);
            }
        }
    }
}

static void launch_gemm(int ep, const __nv_bfloat16* A, int lda,
                        const __nv_bfloat16* B, int ldb,
                        float* C, int ldc, __nv_bfloat16* Cbf, int ldcbf,
                        const float* Res, int ldres,
                        const float* bias, int M, int N, int K) {
    dim3 grd(N / BN, M / BM);
    if (ep == EP_LRELU_BIAS) {
        if (Cbf) {
            cudaFuncSetAttribute(gemm_bf<EP_LRELU_BIAS, 1>, cudaFuncAttributeMaxDynamicSharedMemorySize, GSMEM);
            gemm_bf<EP_LRELU_BIAS, 1><<<grd, 128, GSMEM>>>(A, lda, B, ldb, C, ldc, Cbf, ldcbf, Res, ldres, bias, K);
        } else {
            cudaFuncSetAttribute(gemm_bf<EP_LRELU_BIAS, 0>, cudaFuncAttributeMaxDynamicSharedMemorySize, GSMEM);
            gemm_bf<EP_LRELU_BIAS, 0><<<grd, 128, GSMEM>>>(A, lda, B, ldb, C, ldc, Cbf, ldcbf, Res, ldres, bias, K);
        }
    } else {
        cudaFuncSetAttribute(gemm_bf<EP_RES_OUT, 1>, cudaFuncAttributeMaxDynamicSharedMemorySize, GSMEM);
        gemm_bf<EP_RES_OUT, 1><<<grd, 128, GSMEM>>>(A, lda, B, ldb, C, ldc, Cbf, ldcbf, Res, ldres, bias, K);
    }
}

// ---------------------------------------------------------------------------
// kernel_launch
// ---------------------------------------------------------------------------
extern "C" void kernel_launch(void* const* d_in, const int* in_sizes, int n_in,
                              void* d_out, int out_size) {
    const float* feature = (const float*)d_in[0];
    const float* cw1 = (const float*)d_in[1];  const float* cb1 = (const float*)d_in[2];
    const float* cw2 = (const float*)d_in[3];  const float* cb2 = (const float*)d_in[4];
    const float* cw3 = (const float*)d_in[5];  const float* cb3 = (const float*)d_in[6];
    const float* cw4 = (const float*)d_in[7];  const float* cb4 = (const float*)d_in[8];
    const float* cw5 = (const float*)d_in[9];  const float* cb5 = (const float*)d_in[10];
    const float* w1  = (const float*)d_in[11]; const float* b1  = (const float*)d_in[12];
    const float* m1_vf = (const float*)d_in[13]; const float* m1_gf = (const float*)d_in[14];
    const float* m1_bf = (const float*)d_in[15]; const float* m1_vg = (const float*)d_in[16];
    const float* m1_gg = (const float*)d_in[17]; const float* m1_bg = (const float*)d_in[18];
    const float* w2  = (const float*)d_in[19]; const float* b2  = (const float*)d_in[20];
    const float* m2_vf = (const float*)d_in[21]; const float* m2_gf = (const float*)d_in[22];
    const float* m2_bf = (const float*)d_in[23]; const float* m2_vg = (const float*)d_in[24];
    const float* m2_gg = (const float*)d_in[25]; const float* m2_bg = (const float*)d_in[26];
    const float* w3  = (const float*)d_in[27]; const float* b3  = (const float*)d_in[28];
    float* out = (float*)d_out;

    __nv_bfloat16 *cat, *h2_bf, *wm1F, *wm1G, *wm2F, *wm2G, *w1g, *w2c;
    float *mid, *h2, *conv0, *conv1, *feat, *bias1;
    cudaGetSymbolAddress((void**)&cat,   g_cat);
    cudaGetSymbolAddress((void**)&mid,   g_mid);
    cudaGetSymbolAddress((void**)&h2,    g_h2);
    cudaGetSymbolAddress((void**)&h2_bf, g_h2_bf);
    cudaGetSymbolAddress((void**)&wm1F,  g_wm1F);
    cudaGetSymbolAddress((void**)&wm1G,  g_wm1G);
    cudaGetSymbolAddress((void**)&wm2F,  g_wm2F);
    cudaGetSymbolAddress((void**)&wm2G,  g_wm2G);
    cudaGetSymbolAddress((void**)&w1g,   g_w1g_bf);
    cudaGetSymbolAddress((void**)&w2c,   g_w2cat);
    cudaGetSymbolAddress((void**)&conv0, g_conv0);
    cudaGetSymbolAddress((void**)&conv1, g_conv1);
    cudaGetSymbolAddress((void**)&feat,  g_feat);
    cudaGetSymbolAddress((void**)&bias1, g_bias1);

    // --- positional grid features into cat[:, 0:64] ---
    grid_kernel<<<(NPIX * 64) / 256, 256>>>(cat);

    // --- conv stack (512 threads, 8-way ic split) ---
    conv3x3_kernel<<<768, 512, (448 * 9 + 512) * 4>>>(feature, cw1, cb1, conv0, 1792, 768, 8, 8, 8, 8, 1, 4);
    conv3x3_kernel<<<768, 512, (256 * 9 + 512) * 4>>>(conv0, cw2, cb2, conv1, 768, 768, 8, 8, 8, 8, 1, 3);
    conv3x3_kernel<<<768, 512, (384 * 9 + 512) * 4>>>(conv1, cw3, cb3, conv0, 768, 768, 8, 8, 8, 8, 1, 2);
    conv3x3_kernel<<<768, 512, (256 * 9 + 512) * 4>>>(conv0, cw4, cb4, conv1, 768, 768, 8, 8, 6, 6, 0, 3);
    conv3x3_kernel<<<128, 512, (768 * 9 + 512) * 4>>>(conv1, cw5, cb5, feat, 768, 128, 6, 6, 4, 4, 0, 1);

    // --- fold feat @ w1[:,32:].T + b1 into a bias vector ---
    bias1_kernel<<<128, 256>>>(feat, w1, b1, bias1);

    // --- weight prep (bf16) ---
    wnorm_kernel<<<8 * 512, 128>>>(m1_vf, m1_gf, wm1F, 512);
    wnorm_kernel<<<8 * 512, 128>>>(m1_vg, m1_gg, wm1G, 512);
    wnorm_kernel<<<8 * 256, 128>>>(m2_vf, m2_gf, wm2F, 256);
    wnorm_kernel<<<8 * 256, 128>>>(m2_vg, m2_gg, wm2G, 256);
    conv_w1g_kernel<<<(1024 * 64) / 256, 256>>>(w1, w1g);
    conv_w2cat_kernel<<<(512 * 1088) / 256, 256>>>(w2, w2c);

    // --- mid = lrelu(grid @ w1grid.T + bias1): A = cat[:,0:64] ---
    launch_gemm(EP_LRELU_BIAS, cat, 1088, w1g, 64, mid, 1024, cat + 64, 1088,
                mid, 1024, bias1, NPIX, 1024, 64);

    // --- mem stack 1: halves of 1024 inside cat[:,64:1088] + fp32 mid ---
    for (int s = 0; s < 8; s++) {
        launch_gemm(EP_RES_OUT, cat + 64 + 512, 1088, wm1F + (size_t)s * 512 * 512, 512,
                    mid, 1024, cat + 64, 1088, mid, 1024, m1_bf + s * 512, NPIX, 512, 512);
        launch_gemm(EP_RES_OUT, cat + 64, 1088, wm1G + (size_t)s * 512 * 512, 512,
                    mid + 512, 1024, cat + 64 + 512, 1088, mid + 512, 1024, m1_bg + s * 512, NPIX, 512, 512);
    }

    // --- h2 = lrelu(cat @ w2cat.T + b2): single K=1088 GEMM ---
    launch_gemm(EP_LRELU_BIAS, cat, 1088, w2c, 1088, h2, 512, h2_bf, 512,
                h2, 512, b2, NPIX, 512, 1088);

    // --- mem stack 2: halves of 512 (256 each) ---
    for (int s = 0; s < 8; s++) {
        launch_gemm(EP_RES_OUT, h2_bf + 256, 512, wm2F + (size_t)s * 256 * 256, 256,
                    h2, 512, h2_bf, 512, h2, 512, m2_bf + s * 256, NPIX, 256, 256);
        launch_gemm(EP_RES_OUT, h2_bf, 512, wm2G + (size_t)s * 256 * 256, 256,
                    h2 + 256, 512, h2_bf + 256, 512, h2 + 256, 512, m2_bg + s * 256, NPIX, 256, 256);
    }

    // --- head ---
    head_kernel<<<NPIX / 8, 256>>>(h2, w3, b3, out);
}

// round 10
// speedup vs baseline: 5.4770x; 1.0044x over previous
#include <cuda_runtime.h>
#include <cuda_bf16.h>
#include <cstdint>
#include <math.h>

// ---------------------------------------------------------------------------
// Scratch
// ---------------------------------------------------------------------------
#define NPIX 65536
// concatenated bf16 activations: [grid(64, zero-padded) | mid(1024)]
__device__ __nv_bfloat16 g_cat[NPIX * 1088];
__device__ float         g_mid [NPIX * 1024];         // fp32 residual path
__device__ float         g_h2  [NPIX * 512];
__device__ __nv_bfloat16 g_h2_bf[NPIX * 512];
__device__ __nv_bfloat16 g_wm1F[8 * 512 * 512];
__device__ __nv_bfloat16 g_wm1G[8 * 512 * 512];
__device__ __nv_bfloat16 g_wm2F[8 * 256 * 256];
__device__ __nv_bfloat16 g_wm2G[8 * 256 * 256];
__device__ __nv_bfloat16 g_w1g_bf[1024 * 64];         // w1[:, :32] zero-padded
__device__ __nv_bfloat16 g_w2cat[512 * 1088];         // [w2grid(64pad) | w2mid(1024)]
__device__ float g_conv0[768 * 8 * 8];
__device__ float g_conv1[768 * 8 * 8];
__device__ float g_part[4 * 768 * 64];                // conv ic-chunk partials
__device__ float g_feat[2048];
__device__ float g_bias1[1024];

// ---------------------------------------------------------------------------
// Grid features -> bf16 into g_cat cols [0,64), stride 1088
// ---------------------------------------------------------------------------
__global__ void grid_kernel(__nv_bfloat16* __restrict__ cat) {
    int idx = blockIdx.x * blockDim.x + threadIdx.x;      // n*64 + c
    int n = idx >> 6, c = idx & 63;
    float val = 0.f;
    if (c < 32) {
        int i = n >> 8, j = n & 255;
        float r = (float)(((c & 1) ? j : i) - 128) * (float)(3.14159265358979323846 / 256.0);
        float s = exp2f(0.5f * (float)(c >> 1));
        val = sinf(r * s);
    }
    cat[(size_t)n * 1088 + c] = __float2bfloat16(val);
}

// ---------------------------------------------------------------------------
// Grouped 3x3 conv, split: grid(Cout, 4 ic-chunks), 512 threads, 8-way
// within-block ic split. Writes chunk partial sums (no bias / no lrelu).
// ---------------------------------------------------------------------------
__global__ void conv_part_kernel(const float* __restrict__ in, const float* __restrict__ w,
                                 float* __restrict__ part,
                                 int Cin, int Cout, int Hin, int Win,
                                 int Hout, int Wout, int pad, int groups) {
    int oc = blockIdx.x;
    int chunk = blockIdx.y;                 // 0..3
    int icpg = Cin / groups;
    int ocpg = Cout / groups;
    int grp = oc / ocpg;
    int csz  = icpg / 4;                    // icpg divisible by 4 for all layers
    int base = chunk * csz;

    extern __shared__ float sm[];
    float* sw  = sm;                        // csz*9
    float* red = sm + csz * 9;              // 8*64
    for (int i = threadIdx.x; i < csz * 9; i += blockDim.x)
        sw[i] = w[(size_t)oc * icpg * 9 + base * 9 + i];
    __syncthreads();

    int icq = threadIdx.x >> 6;             // 0..7
    int px  = threadIdx.x & 63;
    float acc = 0.f;
    if (px < Hout * Wout) {
        int oy = px / Wout, ox = px % Wout;
        const float* inb = in + (size_t)grp * icpg * Hin * Win + (size_t)base * Hin * Win;
        for (int ic = icq; ic < csz; ic += 8) {
            const float* ip = inb + (size_t)ic * Hin * Win;
            const float* wp = sw + ic * 9;
            #pragma unroll
            for (int ky = 0; ky < 3; ky++) {
                int iy = oy + ky - pad;
                if (iy < 0 || iy >= Hin) continue;
                #pragma unroll
                for (int kx = 0; kx < 3; kx++) {
                    int ix = ox + kx - pad;
                    if (ix < 0 || ix >= Win) continue;
                    acc = fmaf(ip[iy * Win + ix], wp[ky * 3 + kx], acc);
                }
            }
        }
    }
    red[icq * 64 + px] = acc;
    __syncthreads();
    if (icq == 0 && px < Hout * Wout) {
        float v = red[px];
        #pragma unroll
        for (int q = 1; q < 8; q++) v += red[q * 64 + px];
        part[((size_t)chunk * Cout + oc) * 64 + px] = v;
    }
}

// Reduce 4 chunk partials + bias + leaky_relu -> out[oc*HW + px]
__global__ void conv_reduce_kernel(const float* __restrict__ part,
                                   const float* __restrict__ bias,
                                   float* __restrict__ out, int Cout, int HW) {
    int idx = blockIdx.x * blockDim.x + threadIdx.x;
    if (idx >= Cout * HW) return;
    int oc = idx / HW, px = idx % HW;
    float v = bias[oc];
    #pragma unroll
    for (int c = 0; c < 4; c++)
        v += part[((size_t)c * Cout + oc) * 64 + px];
    out[idx] = v > 0.f ? v : 0.01f * v;
}

__global__ void wnorm_kernel(const float* __restrict__ v, const float* __restrict__ g,
                             __nv_bfloat16* __restrict__ w, int K) {
    int row = blockIdx.x;
    const float* vr = v + (size_t)row * K;
    float s = 0.f;
    for (int k = threadIdx.x; k < K; k += blockDim.x) { float x = vr[k]; s = fmaf(x, x, s); }
    __shared__ float red[128];
    red[threadIdx.x] = s;
    __syncthreads();
    for (int o = 64; o; o >>= 1) {
        if (threadIdx.x < o) red[threadIdx.x] += red[threadIdx.x + o];
        __syncthreads();
    }
    float scale = g[row] / sqrtf(red[0]);
    for (int k = threadIdx.x; k < K; k += blockDim.x)
        w[(size_t)row * K + k] = __float2bfloat16(vr[k] * scale);
}

__global__ void conv_w1g_kernel(const float* __restrict__ w1, __nv_bfloat16* __restrict__ o) {
    int idx = blockIdx.x * blockDim.x + threadIdx.x;   // 1024*64
    int j = idx >> 6, k = idx & 63;
    o[idx] = __float2bfloat16(k < 32 ? w1[(size_t)j * 2080 + k] : 0.f);
}
__global__ void conv_w2cat_kernel(const float* __restrict__ w2, __nv_bfloat16* __restrict__ o) {
    int idx = blockIdx.x * blockDim.x + threadIdx.x;   // 512*1088
    int j = idx / 1088, r = idx % 1088;
    float v;
    if (r < 32)       v = w2[(size_t)j * 1056 + r];
    else if (r < 64)  v = 0.f;
    else              v = w2[(size_t)j * 1056 + 32 + (r - 64)];
    o[idx] = __float2bfloat16(v);
}

__global__ void bias1_kernel(const float* __restrict__ feat, const float* __restrict__ w1,
                             const float* __restrict__ b1, float* __restrict__ out) {
    int j = blockIdx.x * 8 + (threadIdx.x >> 5);
    int lane = threadIdx.x & 31;
    const float* wr = w1 + (size_t)j * 2080 + 32;
    float s = 0.f;
    for (int k = lane; k < 2048; k += 32) s = fmaf(feat[k], wr[k], s);
    #pragma unroll
    for (int o = 16; o; o >>= 1) s += __shfl_down_sync(0xffffffffu, s, o);
    if (lane == 0) out[j] = b1[j] + s;
}

__global__ void head_kernel(const float* __restrict__ h2, const float* __restrict__ w3,
                            const float* __restrict__ b3, float* __restrict__ out) {
    __shared__ float sw[1536];
    for (int i = threadIdx.x; i < 1536; i += blockDim.x) sw[i] = w3[i];
    __syncthreads();
    int n = (blockIdx.x * blockDim.x + threadIdx.x) >> 5;
    int lane = threadIdx.x & 31;
    const float* hr = h2 + (size_t)n * 512;
    float d0 = 0.f, d1 = 0.f, d2 = 0.f;
    for (int t = lane; t < 512; t += 32) {
        float x = hr[t];
        d0 = fmaf(x, sw[t], d0);
        d1 = fmaf(x, sw[512 + t], d1);
        d2 = fmaf(x, sw[1024 + t], d2);
    }
    #pragma unroll
    for (int o = 16; o; o >>= 1) {
        d0 += __shfl_down_sync(0xffffffffu, d0, o);
        d1 += __shfl_down_sync(0xffffffffu, d1, o);
        d2 += __shfl_down_sync(0xffffffffu, d2, o);
    }
    if (lane == 0) {
        out[n]          = 1.1f / (1.f + expf(-(d0 + b3[0]))) - 0.05f;
        out[65536 + n]  = 1.1f / (1.f + expf(-(d1 + b3[1]))) - 0.05f;
        out[131072 + n] = 1.1f / (1.f + expf(-(d2 + b3[2]))) - 0.05f;
    }
}

// ---------------------------------------------------------------------------
// bf16 GEMM: mma.sync.m16n8k16 + ldmatrix + cp.async.
// 128x128 CTA tile, 4 warps (2x2), warp tile 64x64, BK=64, 3 stages (96KB),
// 128 threads, __launch_bounds__(128,2) -> 2 CTAs/SM.
// Fragment double-buffering: kk+1 LDSMs issue under kk's MMAs.
// ---------------------------------------------------------------------------
enum { EP_LRELU_BIAS = 1, EP_RES_OUT = 3 };

#define BM 128
#define BN 128
#define BKB 64
#define STAGES 3
#define OPB (BM * BKB * 2)        // 16 KB
#define STB (2 * OPB)             // 32 KB
#define GSMEM (STAGES * STB)      // 96 KB

__device__ __forceinline__ uint32_t smem_u32(const void* p) {
    uint32_t a;
    asm("{ .reg .u64 t; cvta.to.shared.u64 t, %1; cvt.u32.u64 %0, t; }" : "=r"(a) : "l"(p));
    return a;
}
__device__ __forceinline__ void cp_async16(uint32_t sa, const __nv_bfloat16* g) {
    asm volatile("cp.async.cg.shared.global [%0], [%1], 16;" :: "r"(sa), "l"(g));
}
__device__ __forceinline__ void ldsm4(uint32_t* r, uint32_t addr) {
    asm volatile("ldmatrix.sync.aligned.m8n8.x4.shared.b16 {%0,%1,%2,%3}, [%4];"
                 : "=r"(r[0]), "=r"(r[1]), "=r"(r[2]), "=r"(r[3]) : "r"(addr));
}
__device__ __forceinline__ void mma_bf16(float* c, const uint32_t* a, const uint32_t* b) {
    asm volatile(
        "mma.sync.aligned.m16n8k16.row.col.f32.bf16.bf16.f32 "
        "{%0,%1,%2,%3}, {%4,%5,%6,%7}, {%8,%9}, {%0,%1,%2,%3};"
        : "+f"(c[0]), "+f"(c[1]), "+f"(c[2]), "+f"(c[3])
        : "r"(a[0]), "r"(a[1]), "r"(a[2]), "r"(a[3]), "r"(b[0]), "r"(b[1]));
}
__device__ __forceinline__ uint32_t pack_bf16x2(float lo, float hi) {
    uint32_t u;
    asm("cvt.rn.bf16x2.f32 %0, %1, %2;" : "=r"(u) : "f"(hi), "f"(lo));
    return u;
}

template <int EP, int WBF>
__global__ __launch_bounds__(128, 2)
void gemm_bf(const __nv_bfloat16* __restrict__ A, int lda,
             const __nv_bfloat16* __restrict__ B, int ldb,
             float* __restrict__ C, int ldc,
             __nv_bfloat16* __restrict__ Cbf, int ldcbf,
             const float* __restrict__ Res, int ldres,
             const float* __restrict__ bias, int K) {
    extern __shared__ char smem[];
    uint32_t sbase = smem_u32(smem);

    int tid = threadIdx.x;
    int wid = tid >> 5, lane = tid & 31;
    int g = lane >> 2, tg = lane & 3;
    int wm = (wid >> 1) * 64;
    int wn = (wid & 1) * 64;

    long brow = blockIdx.y, bcol = blockIdx.x;
    const __nv_bfloat16* Ab = A + brow * BM * (long)lda;
    const __nv_bfloat16* Bb = B + bcol * BN * (long)ldb;
    C   += brow * BM * (long)ldc   + bcol * BN;
    if (WBF) Cbf += brow * BM * (long)ldcbf + bcol * BN;
    Res += brow * BM * (long)ldres + bcol * BN;
    const float* biasp = bias + bcol * BN;

    // ldmatrix address components (byte offsets within 128-row x 128B tile)
    uint32_t aRow[4], aXor[4], bRow[4], bXor[4];
    uint32_t akb = (lane >> 4) * 16;
    uint32_t bkb = ((lane >> 3) & 1) * 16;
    #pragma unroll
    for (int s = 0; s < 4; s++) {
        uint32_t r = wm + s * 16 + (lane & 15);
        aRow[s] = r * 128;
        aXor[s] = (r & 7) << 4;
    }
    #pragma unroll
    for (int p = 0; p < 4; p++) {
        uint32_t r = wn + p * 16 + ((lane >> 4) << 3) + (lane & 7);
        bRow[p] = r * 128;
        bXor[p] = (r & 7) << 4;
    }

    float acc[4][8][4];
    #pragma unroll
    for (int s = 0; s < 4; s++)
        #pragma unroll
        for (int nt = 0; nt < 8; nt++)
            #pragma unroll
            for (int q = 0; q < 4; q++) acc[s][nt][q] = 0.f;

    int T = K / BKB;

    // loader: 1024 16B-chunks per operand tile, 8 per thread per operand
    auto load_stage = [&](int u, int st) {
        const __nv_bfloat16* Ag = Ab + u * BKB;
        const __nv_bfloat16* Bg = Bb + u * BKB;
        uint32_t sA = sbase + st * STB;
        uint32_t sB = sA + OPB;
        #pragma unroll
        for (int j = 0; j < 8; j++) {
            int idx = tid + 128 * j;
            int r = idx >> 3, c = idx & 7;
            uint32_t sw = r * 128 + ((c * 16) ^ ((r & 7) << 4));
            cp_async16(sA + sw, Ag + (long)r * lda + c * 8);
            cp_async16(sB + sw, Bg + (long)r * ldb + c * 8);
        }
    };

    // fragment loader for one kk slice
    auto load_frags = [&](uint32_t sA, uint32_t sB, int kk,
                          uint32_t af[4][4], uint32_t bp[4][4]) {
        #pragma unroll
        for (int s = 0; s < 4; s++)
            ldsm4(af[s], sA + aRow[s] + (((kk * 32) + akb) ^ aXor[s]));
        #pragma unroll
        for (int p = 0; p < 4; p++)
            ldsm4(bp[p], sB + bRow[p] + (((kk * 32) + bkb) ^ bXor[p]));
    };

    #pragma unroll
    for (int p = 0; p < STAGES - 1; p++) {
        if (p < T) load_stage(p, p);
        asm volatile("cp.async.commit_group;");
    }

    uint32_t af[2][4][4], bp[2][4][4];

    for (int t = 0; t < T; t++) {
        asm volatile("cp.async.wait_group %0;" :: "n"(STAGES - 2));
        __syncthreads();
        int u = t + STAGES - 1;
        if (u < T) load_stage(u, u % STAGES);
        asm volatile("cp.async.commit_group;");

        uint32_t sA = sbase + (t % STAGES) * STB;
        uint32_t sB = sA + OPB;

        load_frags(sA, sB, 0, af[0], bp[0]);
        #pragma unroll
        for (int kk = 0; kk < 4; kk++) {
            int cur = kk & 1, nxt = cur ^ 1;
            if (kk < 3) load_frags(sA, sB, kk + 1, af[nxt], bp[nxt]);
            #pragma unroll
            for (int s = 0; s < 4; s++)
                #pragma unroll
                for (int p = 0; p < 4; p++) {
                    mma_bf16(acc[s][p * 2 + 0], af[cur][s], &bp[cur][p][0]);
                    mma_bf16(acc[s][p * 2 + 1], af[cur][s], &bp[cur][p][2]);
                }
        }
    }

    // epilogue
    #pragma unroll
    for (int s = 0; s < 4; s++) {
        #pragma unroll
        for (int half = 0; half < 2; half++) {
            long row = wm + s * 16 + g + half * 8;
            #pragma unroll
            for (int nt = 0; nt < 8; nt++) {
                int col = wn + nt * 8 + tg * 2;
                float v0 = acc[s][nt][half * 2 + 0];
                float v1 = acc[s][nt][half * 2 + 1];
                if (EP == EP_LRELU_BIAS) {
                    v0 += biasp[col]; v1 += biasp[col + 1];
                    v0 = v0 > 0.f ? v0 : 0.01f * v0;
                    v1 = v1 > 0.f ? v1 : 0.01f * v1;
                } else {  // EP_RES_OUT
                    v0 += biasp[col]; v1 += biasp[col + 1];
                    v0 = v0 > 0.f ? v0 : 0.01f * v0;
                    v1 = v1 > 0.f ? v1 : 0.01f * v1;
                    float2 r = *reinterpret_cast<const float2*>(Res + row * ldres + col);
                    v0 += r.x; v1 += r.y;
                }
                float2 o; o.x = v0; o.y = v1;
                *reinterpret_cast<float2*>(C + row * ldc + col) = o;
                if (WBF)
                    *reinterpret_cast<uint32_t*>(Cbf + row * ldcbf + col) = pack_bf16x2(v0, v1);
            }
        }
    }
}

static void launch_gemm(int ep, const __nv_bfloat16* A, int lda,
                        const __nv_bfloat16* B, int ldb,
                        float* C, int ldc, __nv_bfloat16* Cbf, int ldcbf,
                        const float* Res, int ldres,
                        const float* bias, int M, int N, int K) {
    dim3 grd(N / BN, M / BM);
    if (ep == EP_LRELU_BIAS) {
        if (Cbf) {
            cudaFuncSetAttribute(gemm_bf<EP_LRELU_BIAS, 1>, cudaFuncAttributeMaxDynamicSharedMemorySize, GSMEM);
            gemm_bf<EP_LRELU_BIAS, 1><<<grd, 128, GSMEM>>>(A, lda, B, ldb, C, ldc, Cbf, ldcbf, Res, ldres, bias, K);
        } else {
            cudaFuncSetAttribute(gemm_bf<EP_LRELU_BIAS, 0>, cudaFuncAttributeMaxDynamicSharedMemorySize, GSMEM);
            gemm_bf<EP_LRELU_BIAS, 0><<<grd, 128, GSMEM>>>(A, lda, B, ldb, C, ldc, Cbf, ldcbf, Res, ldres, bias, K);
        }
    } else {
        cudaFuncSetAttribute(gemm_bf<EP_RES_OUT, 1>, cudaFuncAttributeMaxDynamicSharedMemorySize, GSMEM);
        gemm_bf<EP_RES_OUT, 1><<<grd, 128, GSMEM>>>(A, lda, B, ldb, C, ldc, Cbf, ldcbf, Res, ldres, bias, K);
    }
}

// conv helper: split conv + reduce
static void launch_conv(const float* in, const float* w, const float* bias, float* out,
                        float* part, int Cin, int Cout, int Hin, int Win,
                        int Hout, int Wout, int pad, int groups) {
    int icpg = Cin / groups;
    int csz  = icpg / 4;
    int smem = (csz * 9 + 512) * 4;
    conv_part_kernel<<<dim3(Cout, 4), 512, smem>>>(in, w, part, Cin, Cout,
                                                   Hin, Win, Hout, Wout, pad, groups);
    int total = Cout * Hout * Wout;
    conv_reduce_kernel<<<(total + 255) / 256, 256>>>(part, bias, out, Cout, Hout * Wout);
}

// ---------------------------------------------------------------------------
// kernel_launch
// ---------------------------------------------------------------------------
extern "C" void kernel_launch(void* const* d_in, const int* in_sizes, int n_in,
                              void* d_out, int out_size) {
    const float* feature = (const float*)d_in[0];
    const float* cw1 = (const float*)d_in[1];  const float* cb1 = (const float*)d_in[2];
    const float* cw2 = (const float*)d_in[3];  const float* cb2 = (const float*)d_in[4];
    const float* cw3 = (const float*)d_in[5];  const float* cb3 = (const float*)d_in[6];
    const float* cw4 = (const float*)d_in[7];  const float* cb4 = (const float*)d_in[8];
    const float* cw5 = (const float*)d_in[9];  const float* cb5 = (const float*)d_in[10];
    const float* w1  = (const float*)d_in[11]; const float* b1  = (const float*)d_in[12];
    const float* m1_vf = (const float*)d_in[13]; const float* m1_gf = (const float*)d_in[14];
    const float* m1_bf = (const float*)d_in[15]; const float* m1_vg = (const float*)d_in[16];
    const float* m1_gg = (const float*)d_in[17]; const float* m1_bg = (const float*)d_in[18];
    const float* w2  = (const float*)d_in[19]; const float* b2  = (const float*)d_in[20];
    const float* m2_vf = (const float*)d_in[21]; const float* m2_gf = (const float*)d_in[22];
    const float* m2_bf = (const float*)d_in[23]; const float* m2_vg = (const float*)d_in[24];
    const float* m2_gg = (const float*)d_in[25]; const float* m2_bg = (const float*)d_in[26];
    const float* w3  = (const float*)d_in[27]; const float* b3  = (const float*)d_in[28];
    float* out = (float*)d_out;

    __nv_bfloat16 *cat, *h2_bf, *wm1F, *wm1G, *wm2F, *wm2G, *w1g, *w2c;
    float *mid, *h2, *conv0, *conv1, *part, *feat, *bias1;
    cudaGetSymbolAddress((void**)&cat,   g_cat);
    cudaGetSymbolAddress((void**)&mid,   g_mid);
    cudaGetSymbolAddress((void**)&h2,    g_h2);
    cudaGetSymbolAddress((void**)&h2_bf, g_h2_bf);
    cudaGetSymbolAddress((void**)&wm1F,  g_wm1F);
    cudaGetSymbolAddress((void**)&wm1G,  g_wm1G);
    cudaGetSymbolAddress((void**)&wm2F,  g_wm2F);
    cudaGetSymbolAddress((void**)&wm2G,  g_wm2G);
    cudaGetSymbolAddress((void**)&w1g,   g_w1g_bf);
    cudaGetSymbolAddress((void**)&w2c,   g_w2cat);
    cudaGetSymbolAddress((void**)&conv0, g_conv0);
    cudaGetSymbolAddress((void**)&conv1, g_conv1);
    cudaGetSymbolAddress((void**)&part,  g_part);
    cudaGetSymbolAddress((void**)&feat,  g_feat);
    cudaGetSymbolAddress((void**)&bias1, g_bias1);

    // --- positional grid features into cat[:, 0:64] ---
    grid_kernel<<<(NPIX * 64) / 256, 256>>>(cat);

    // --- conv stack (split across 4 ic-chunk blocks + reduce) ---
    launch_conv(feature, cw1, cb1, conv0, part, 1792, 768, 8, 8, 8, 8, 1, 4);
    launch_conv(conv0,   cw2, cb2, conv1, part, 768,  768, 8, 8, 8, 8, 1, 3);
    launch_conv(conv1,   cw3, cb3, conv0, part, 768,  768, 8, 8, 8, 8, 1, 2);
    launch_conv(conv0,   cw4, cb4, conv1, part, 768,  768, 8, 8, 6, 6, 0, 3);
    launch_conv(conv1,   cw5, cb5, feat,  part, 768,  128, 6, 6, 4, 4, 0, 1);

    // --- fold feat @ w1[:,32:].T + b1 into a bias vector ---
    bias1_kernel<<<128, 256>>>(feat, w1, b1, bias1);

    // --- weight prep (bf16) ---
    wnorm_kernel<<<8 * 512, 128>>>(m1_vf, m1_gf, wm1F, 512);
    wnorm_kernel<<<8 * 512, 128>>>(m1_vg, m1_gg, wm1G, 512);
    wnorm_kernel<<<8 * 256, 128>>>(m2_vf, m2_gf, wm2F, 256);
    wnorm_kernel<<<8 * 256, 128>>>(m2_vg, m2_gg, wm2G, 256);
    conv_w1g_kernel<<<(1024 * 64) / 256, 256>>>(w1, w1g);
    conv_w2cat_kernel<<<(512 * 1088) / 256, 256>>>(w2, w2c);

    // --- mid = lrelu(grid @ w1grid.T + bias1): A = cat[:,0:64] ---
    launch_gemm(EP_LRELU_BIAS, cat, 1088, w1g, 64, mid, 1024, cat + 64, 1088,
                mid, 1024, bias1, NPIX, 1024, 64);

    // --- mem stack 1: halves of 1024 inside cat[:,64:1088] + fp32 mid ---
    for (int s = 0; s < 8; s++) {
        launch_gemm(EP_RES_OUT, cat + 64 + 512, 1088, wm1F + (size_t)s * 512 * 512, 512,
                    mid, 1024, cat + 64, 1088, mid, 1024, m1_bf + s * 512, NPIX, 512, 512);
        launch_gemm(EP_RES_OUT, cat + 64, 1088, wm1G + (size_t)s * 512 * 512, 512,
                    mid + 512, 1024, cat + 64 + 512, 1088, mid + 512, 1024, m1_bg + s * 512, NPIX, 512, 512);
    }

    // --- h2 = lrelu(cat @ w2cat.T + b2): single K=1088 GEMM ---
    launch_gemm(EP_LRELU_BIAS, cat, 1088, w2c, 1088, h2, 512, h2_bf, 512,
                h2, 512, b2, NPIX, 512, 1088);

    // --- mem stack 2: halves of 512 (256 each) ---
    for (int s = 0; s < 8; s++) {
        launch_gemm(EP_RES_OUT, h2_bf + 256, 512, wm2F + (size_t)s * 256 * 256, 256,
                    h2, 512, h2_bf, 512, h2, 512, m2_bf + s * 256, NPIX, 256, 256);
        launch_gemm(EP_RES_OUT, h2_bf, 512, wm2G + (size_t)s * 256 * 256, 256,
                    h2 + 256, 512, h2_bf + 256, 512, h2 + 256, 512, m2_bg + s * 256, NPIX, 256, 256);
    }

    // --- head ---
    head_kernel<<<NPIX / 8, 256>>>(h2, w3, b3, out);
}

// round 11
// speedup vs baseline: 5.5480x; 1.0129x over previous
#include <cuda_runtime.h>
#include <cuda_bf16.h>
#include <cstdint>
#include <math.h>

// ---------------------------------------------------------------------------
// Scratch
// ---------------------------------------------------------------------------
#define NPIX 65536
// concatenated bf16 activations: [grid(64, zero-padded) | mid(1024)]
__device__ __nv_bfloat16 g_cat[NPIX * 1088];
__device__ float         g_mid [NPIX * 1024];         // fp32 residual path
__device__ float         g_h2  [NPIX * 512];
__device__ __nv_bfloat16 g_h2_bf[NPIX * 512];
__device__ __nv_bfloat16 g_wm1F[8 * 512 * 512];
__device__ __nv_bfloat16 g_wm1G[8 * 512 * 512];
__device__ __nv_bfloat16 g_wm2F[8 * 256 * 256];
__device__ __nv_bfloat16 g_wm2G[8 * 256 * 256];
__device__ __nv_bfloat16 g_w1g_bf[1024 * 64];         // w1[:, :32] zero-padded
__device__ __nv_bfloat16 g_w2cat[512 * 1088];         // [w2grid(64pad) | w2mid(1024)]
__device__ float g_conv0[768 * 8 * 8];
__device__ float g_conv1[768 * 8 * 8];
__device__ float g_pad [1792 * 100];                  // zero-padded conv input (10x10)
__device__ float g_part[4 * 768 * 64];                // conv ic-chunk partials
__device__ float g_feat[2048];
__device__ float g_bias1[1024];

// ---------------------------------------------------------------------------
// Grid features -> bf16 into g_cat cols [0,64), stride 1088
// ---------------------------------------------------------------------------
__global__ void grid_kernel(__nv_bfloat16* __restrict__ cat) {
    int idx = blockIdx.x * blockDim.x + threadIdx.x;      // n*64 + c
    int n = idx >> 6, c = idx & 63;
    float val = 0.f;
    if (c < 32) {
        int i = n >> 8, j = n & 255;
        float r = (float)(((c & 1) ? j : i) - 128) * (float)(3.14159265358979323846 / 256.0);
        float s = exp2f(0.5f * (float)(c >> 1));
        val = sinf(r * s);
    }
    cat[(size_t)n * 1088 + c] = __float2bfloat16(val);
}

// ---------------------------------------------------------------------------
// Zero-pad [C,8,8] -> [C,10,10]
// ---------------------------------------------------------------------------
__global__ void pad_kernel(const float* __restrict__ in, float* __restrict__ out, int C) {
    int idx = blockIdx.x * blockDim.x + threadIdx.x;      // c*100 + iy*10 + ix
    if (idx >= C * 100) return;
    int c = idx / 100, r = idx % 100;
    int iy = r / 10, ix = r % 10;
    float v = 0.f;
    if (iy >= 1 && iy <= 8 && ix >= 1 && ix <= 8)
        v = in[c * 64 + (iy - 1) * 8 + (ix - 1)];
    out[idx] = v;
}

// ---------------------------------------------------------------------------
// Grouped 3x3 conv, branch-free taps (input pre-padded or valid-mode).
// grid(Cout, 4 ic-chunks), 512 threads, 8-way within-block ic split.
// Writes chunk partial sums.  Tap offset = (oy+ky)*rowStride + ox+kx.
// ---------------------------------------------------------------------------
__global__ void conv_part_kernel(const float* __restrict__ in, const float* __restrict__ w,
                                 float* __restrict__ part,
                                 int Cout, int icpg, int ocpg,
                                 int rowStride, int chStride,
                                 int Hout, int Wout) {
    int oc = blockIdx.x;
    int chunk = blockIdx.y;                 // 0..3
    int grp = oc / ocpg;
    int csz  = icpg / 4;
    int base = chunk * csz;

    extern __shared__ float sm[];
    float* sw  = sm;                        // csz*9
    float* red = sm + csz * 9;              // 8*64
    for (int i = threadIdx.x; i < csz * 9; i += blockDim.x)
        sw[i] = w[(size_t)oc * icpg * 9 + base * 9 + i];
    __syncthreads();

    int icq = threadIdx.x >> 6;             // 0..7
    int px  = threadIdx.x & 63;
    float acc = 0.f;
    if (px < Hout * Wout) {
        int oy = px / Wout, ox = px % Wout;
        const float* inb = in + (size_t)(grp * icpg + base) * chStride
                              + oy * rowStride + ox;
        for (int ic = icq; ic < csz; ic += 8) {
            const float* ip = inb + (size_t)ic * chStride;
            const float* wp = sw + ic * 9;
            #pragma unroll
            for (int ky = 0; ky < 3; ky++)
                #pragma unroll
                for (int kx = 0; kx < 3; kx++)
                    acc = fmaf(ip[ky * rowStride + kx], wp[ky * 3 + kx], acc);
        }
    }
    red[icq * 64 + px] = acc;
    __syncthreads();
    if (icq == 0 && px < Hout * Wout) {
        float v = red[px];
        #pragma unroll
        for (int q = 1; q < 8; q++) v += red[q * 64 + px];
        part[((size_t)chunk * Cout + oc) * 64 + px] = v;
    }
}

// Reduce 4 chunk partials + bias + leaky_relu -> out[oc*HW + px]
__global__ void conv_reduce_kernel(const float* __restrict__ part,
                                   const float* __restrict__ bias,
                                   float* __restrict__ out, int Cout, int HW) {
    int idx = blockIdx.x * blockDim.x + threadIdx.x;
    if (idx >= Cout * HW) return;
    int oc = idx / HW, px = idx % HW;
    float v = bias[oc];
    #pragma unroll
    for (int c = 0; c < 4; c++)
        v += part[((size_t)c * Cout + oc) * 64 + px];
    out[idx] = v > 0.f ? v : 0.01f * v;
}

__global__ void wnorm_kernel(const float* __restrict__ v, const float* __restrict__ g,
                             __nv_bfloat16* __restrict__ w, int K) {
    int row = blockIdx.x;
    const float* vr = v + (size_t)row * K;
    float s = 0.f;
    for (int k = threadIdx.x; k < K; k += blockDim.x) { float x = vr[k]; s = fmaf(x, x, s); }
    __shared__ float red[128];
    red[threadIdx.x] = s;
    __syncthreads();
    for (int o = 64; o; o >>= 1) {
        if (threadIdx.x < o) red[threadIdx.x] += red[threadIdx.x + o];
        __syncthreads();
    }
    float scale = g[row] / sqrtf(red[0]);
    for (int k = threadIdx.x; k < K; k += blockDim.x)
        w[(size_t)row * K + k] = __float2bfloat16(vr[k] * scale);
}

__global__ void conv_w1g_kernel(const float* __restrict__ w1, __nv_bfloat16* __restrict__ o) {
    int idx = blockIdx.x * blockDim.x + threadIdx.x;   // 1024*64
    int j = idx >> 6, k = idx & 63;
    o[idx] = __float2bfloat16(k < 32 ? w1[(size_t)j * 2080 + k] : 0.f);
}
__global__ void conv_w2cat_kernel(const float* __restrict__ w2, __nv_bfloat16* __restrict__ o) {
    int idx = blockIdx.x * blockDim.x + threadIdx.x;   // 512*1088
    int j = idx / 1088, r = idx % 1088;
    float v;
    if (r < 32)       v = w2[(size_t)j * 1056 + r];
    else if (r < 64)  v = 0.f;
    else              v = w2[(size_t)j * 1056 + 32 + (r - 64)];
    o[idx] = __float2bfloat16(v);
}

__global__ void bias1_kernel(const float* __restrict__ feat, const float* __restrict__ w1,
                             const float* __restrict__ b1, float* __restrict__ out) {
    int j = blockIdx.x * 8 + (threadIdx.x >> 5);
    int lane = threadIdx.x & 31;
    const float* wr = w1 + (size_t)j * 2080 + 32;
    float s = 0.f;
    for (int k = lane; k < 2048; k += 32) s = fmaf(feat[k], wr[k], s);
    #pragma unroll
    for (int o = 16; o; o >>= 1) s += __shfl_down_sync(0xffffffffu, s, o);
    if (lane == 0) out[j] = b1[j] + s;
}

// head reads bf16 shadow of h2 (halves read traffic)
__global__ void head_kernel(const __nv_bfloat16* __restrict__ h2bf,
                            const float* __restrict__ w3,
                            const float* __restrict__ b3, float* __restrict__ out) {
    __shared__ float sw[1536];
    for (int i = threadIdx.x; i < 1536; i += blockDim.x) sw[i] = w3[i];
    __syncthreads();
    int n = (blockIdx.x * blockDim.x + threadIdx.x) >> 5;
    int lane = threadIdx.x & 31;
    const __nv_bfloat16* hr = h2bf + (size_t)n * 512;
    float d0 = 0.f, d1 = 0.f, d2 = 0.f;
    for (int t = lane; t < 512; t += 32) {
        float x = __bfloat162float(hr[t]);
        d0 = fmaf(x, sw[t], d0);
        d1 = fmaf(x, sw[512 + t], d1);
        d2 = fmaf(x, sw[1024 + t], d2);
    }
    #pragma unroll
    for (int o = 16; o; o >>= 1) {
        d0 += __shfl_down_sync(0xffffffffu, d0, o);
        d1 += __shfl_down_sync(0xffffffffu, d1, o);
        d2 += __shfl_down_sync(0xffffffffu, d2, o);
    }
    if (lane == 0) {
        out[n]          = 1.1f / (1.f + expf(-(d0 + b3[0]))) - 0.05f;
        out[65536 + n]  = 1.1f / (1.f + expf(-(d1 + b3[1]))) - 0.05f;
        out[131072 + n] = 1.1f / (1.f + expf(-(d2 + b3[2]))) - 0.05f;
    }
}

// ---------------------------------------------------------------------------
// bf16 GEMM: mma.sync.m16n8k16 + ldmatrix + cp.async.
// 128x128 CTA tile, 4 warps (2x2), warp tile 64x64, BK=64, 3 stages (96KB),
// 128 threads, __launch_bounds__(128,2) -> 2 CTAs/SM.
// Fragment double-buffering: kk+1 LDSMs issue under kk's MMAs.
// ---------------------------------------------------------------------------
enum { EP_LRELU_BIAS = 1, EP_RES_OUT = 3 };

#define BM 128
#define BN 128
#define BKB 64
#define STAGES 3
#define OPB (BM * BKB * 2)        // 16 KB
#define STB (2 * OPB)             // 32 KB
#define GSMEM (STAGES * STB)      // 96 KB

__device__ __forceinline__ uint32_t smem_u32(const void* p) {
    uint32_t a;
    asm("{ .reg .u64 t; cvta.to.shared.u64 t, %1; cvt.u32.u64 %0, t; }" : "=r"(a) : "l"(p));
    return a;
}
__device__ __forceinline__ void cp_async16(uint32_t sa, const __nv_bfloat16* g) {
    asm volatile("cp.async.cg.shared.global [%0], [%1], 16;" :: "r"(sa), "l"(g));
}
__device__ __forceinline__ void ldsm4(uint32_t* r, uint32_t addr) {
    asm volatile("ldmatrix.sync.aligned.m8n8.x4.shared.b16 {%0,%1,%2,%3}, [%4];"
                 : "=r"(r[0]), "=r"(r[1]), "=r"(r[2]), "=r"(r[3]) : "r"(addr));
}
__device__ __forceinline__ void mma_bf16(float* c, const uint32_t* a, const uint32_t* b) {
    asm volatile(
        "mma.sync.aligned.m16n8k16.row.col.f32.bf16.bf16.f32 "
        "{%0,%1,%2,%3}, {%4,%5,%6,%7}, {%8,%9}, {%0,%1,%2,%3};"
        : "+f"(c[0]), "+f"(c[1]), "+f"(c[2]), "+f"(c[3])
        : "r"(a[0]), "r"(a[1]), "r"(a[2]), "r"(a[3]), "r"(b[0]), "r"(b[1]));
}
__device__ __forceinline__ uint32_t pack_bf16x2(float lo, float hi) {
    uint32_t u;
    asm("cvt.rn.bf16x2.f32 %0, %1, %2;" : "=r"(u) : "f"(hi), "f"(lo));
    return u;
}

template <int EP, int WBF>
__global__ __launch_bounds__(128, 2)
void gemm_bf(const __nv_bfloat16* __restrict__ A, int lda,
             const __nv_bfloat16* __restrict__ B, int ldb,
             float* __restrict__ C, int ldc,
             __nv_bfloat16* __restrict__ Cbf, int ldcbf,
             const float* __restrict__ Res, int ldres,
             const float* __restrict__ bias, int K) {
    extern __shared__ char smem[];
    uint32_t sbase = smem_u32(smem);

    int tid = threadIdx.x;
    int wid = tid >> 5, lane = tid & 31;
    int g = lane >> 2, tg = lane & 3;
    int wm = (wid >> 1) * 64;
    int wn = (wid & 1) * 64;

    long brow = blockIdx.y, bcol = blockIdx.x;
    const __nv_bfloat16* Ab = A + brow * BM * (long)lda;
    const __nv_bfloat16* Bb = B + bcol * BN * (long)ldb;
    C   += brow * BM * (long)ldc   + bcol * BN;
    if (WBF) Cbf += brow * BM * (long)ldcbf + bcol * BN;
    Res += brow * BM * (long)ldres + bcol * BN;
    const float* biasp = bias + bcol * BN;

    // ldmatrix address components (byte offsets within 128-row x 128B tile)
    uint32_t aRow[4], aXor[4], bRow[4], bXor[4];
    uint32_t akb = (lane >> 4) * 16;
    uint32_t bkb = ((lane >> 3) & 1) * 16;
    #pragma unroll
    for (int s = 0; s < 4; s++) {
        uint32_t r = wm + s * 16 + (lane & 15);
        aRow[s] = r * 128;
        aXor[s] = (r & 7) << 4;
    }
    #pragma unroll
    for (int p = 0; p < 4; p++) {
        uint32_t r = wn + p * 16 + ((lane >> 4) << 3) + (lane & 7);
        bRow[p] = r * 128;
        bXor[p] = (r & 7) << 4;
    }

    float acc[4][8][4];
    #pragma unroll
    for (int s = 0; s < 4; s++)
        #pragma unroll
        for (int nt = 0; nt < 8; nt++)
            #pragma unroll
            for (int q = 0; q < 4; q++) acc[s][nt][q] = 0.f;

    int T = K / BKB;

    // loader: 1024 16B-chunks per operand tile, 8 per thread per operand
    auto load_stage = [&](int u, int st) {
        const __nv_bfloat16* Ag = Ab + u * BKB;
        const __nv_bfloat16* Bg = Bb + u * BKB;
        uint32_t sA = sbase + st * STB;
        uint32_t sB = sA + OPB;
        #pragma unroll
        for (int j = 0; j < 8; j++) {
            int idx = tid + 128 * j;
            int r = idx >> 3, c = idx & 7;
            uint32_t sw = r * 128 + ((c * 16) ^ ((r & 7) << 4));
            cp_async16(sA + sw, Ag + (long)r * lda + c * 8);
            cp_async16(sB + sw, Bg + (long)r * ldb + c * 8);
        }
    };

    // fragment loader for one kk slice
    auto load_frags = [&](uint32_t sA, uint32_t sB, int kk,
                          uint32_t af[4][4], uint32_t bp[4][4]) {
        #pragma unroll
        for (int s = 0; s < 4; s++)
            ldsm4(af[s], sA + aRow[s] + (((kk * 32) + akb) ^ aXor[s]));
        #pragma unroll
        for (int p = 0; p < 4; p++)
            ldsm4(bp[p], sB + bRow[p] + (((kk * 32) + bkb) ^ bXor[p]));
    };

    #pragma unroll
    for (int p = 0; p < STAGES - 1; p++) {
        if (p < T) load_stage(p, p);
        asm volatile("cp.async.commit_group;");
    }

    uint32_t af[2][4][4], bp[2][4][4];

    for (int t = 0; t < T; t++) {
        asm volatile("cp.async.wait_group %0;" :: "n"(STAGES - 2));
        __syncthreads();
        int u = t + STAGES - 1;
        if (u < T) load_stage(u, u % STAGES);
        asm volatile("cp.async.commit_group;");

        uint32_t sA = sbase + (t % STAGES) * STB;
        uint32_t sB = sA + OPB;

        load_frags(sA, sB, 0, af[0], bp[0]);
        #pragma unroll
        for (int kk = 0; kk < 4; kk++) {
            int cur = kk & 1, nxt = cur ^ 1;
            if (kk < 3) load_frags(sA, sB, kk + 1, af[nxt], bp[nxt]);
            #pragma unroll
            for (int s = 0; s < 4; s++)
                #pragma unroll
                for (int p = 0; p < 4; p++) {
                    mma_bf16(acc[s][p * 2 + 0], af[cur][s], &bp[cur][p][0]);
                    mma_bf16(acc[s][p * 2 + 1], af[cur][s], &bp[cur][p][2]);
                }
        }
    }

    // epilogue
    #pragma unroll
    for (int s = 0; s < 4; s++) {
        #pragma unroll
        for (int half = 0; half < 2; half++) {
            long row = wm + s * 16 + g + half * 8;
            #pragma unroll
            for (int nt = 0; nt < 8; nt++) {
                int col = wn + nt * 8 + tg * 2;
                float v0 = acc[s][nt][half * 2 + 0];
                float v1 = acc[s][nt][half * 2 + 1];
                if (EP == EP_LRELU_BIAS) {
                    v0 += biasp[col]; v1 += biasp[col + 1];
                    v0 = v0 > 0.f ? v0 : 0.01f * v0;
                    v1 = v1 > 0.f ? v1 : 0.01f * v1;
                } else {  // EP_RES_OUT
                    v0 += biasp[col]; v1 += biasp[col + 1];
                    v0 = v0 > 0.f ? v0 : 0.01f * v0;
                    v1 = v1 > 0.f ? v1 : 0.01f * v1;
                    float2 r = *reinterpret_cast<const float2*>(Res + row * ldres + col);
                    v0 += r.x; v1 += r.y;
                }
                float2 o; o.x = v0; o.y = v1;
                *reinterpret_cast<float2*>(C + row * ldc + col) = o;
                if (WBF)
                    *reinterpret_cast<uint32_t*>(Cbf + row * ldcbf + col) = pack_bf16x2(v0, v1);
            }
        }
    }
}

static void launch_gemm(int ep, const __nv_bfloat16* A, int lda,
                        const __nv_bfloat16* B, int ldb,
                        float* C, int ldc, __nv_bfloat16* Cbf, int ldcbf,
                        const float* Res, int ldres,
                        const float* bias, int M, int N, int K) {
    dim3 grd(N / BN, M / BM);
    if (ep == EP_LRELU_BIAS) {
        if (Cbf) {
            cudaFuncSetAttribute(gemm_bf<EP_LRELU_BIAS, 1>, cudaFuncAttributeMaxDynamicSharedMemorySize, GSMEM);
            gemm_bf<EP_LRELU_BIAS, 1><<<grd, 128, GSMEM>>>(A, lda, B, ldb, C, ldc, Cbf, ldcbf, Res, ldres, bias, K);
        } else {
            cudaFuncSetAttribute(gemm_bf<EP_LRELU_BIAS, 0>, cudaFuncAttributeMaxDynamicSharedMemorySize, GSMEM);
            gemm_bf<EP_LRELU_BIAS, 0><<<grd, 128, GSMEM>>>(A, lda, B, ldb, C, ldc, Cbf, ldcbf, Res, ldres, bias, K);
        }
    } else {
        cudaFuncSetAttribute(gemm_bf<EP_RES_OUT, 1>, cudaFuncAttributeMaxDynamicSharedMemorySize, GSMEM);
        gemm_bf<EP_RES_OUT, 1><<<grd, 128, GSMEM>>>(A, lda, B, ldb, C, ldc, Cbf, ldcbf, Res, ldres, bias, K);
    }
}

// conv helper: optional pad + split conv + reduce
static void launch_conv(const float* in, const float* w, const float* bias, float* out,
                        float* part, float* padbuf,
                        int Cin, int Cout, int Hin, int Win,
                        int Hout, int Wout, int pad, int groups) {
    int icpg = Cin / groups;
    int ocpg = Cout / groups;
    int csz  = icpg / 4;
    int smem = (csz * 9 + 512) * 4;
    const float* src = in;
    int rowStride, chStride;
    if (pad == 1) {
        pad_kernel<<<(Cin * 100 + 255) / 256, 256>>>(in, padbuf, Cin);
        src = padbuf;
        rowStride = 10; chStride = 100;
    } else {
        rowStride = Win; chStride = Hin * Win;
    }
    conv_part_kernel<<<dim3(Cout, 4), 512, smem>>>(src, w, part, Cout, icpg, ocpg,
                                                   rowStride, chStride, Hout, Wout);
    int total = Cout * Hout * Wout;
    conv_reduce_kernel<<<(total + 255) / 256, 256>>>(part, bias, out, Cout, Hout * Wout);
}

// ---------------------------------------------------------------------------
// kernel_launch
// ---------------------------------------------------------------------------
extern "C" void kernel_launch(void* const* d_in, const int* in_sizes, int n_in,
                              void* d_out, int out_size) {
    const float* feature = (const float*)d_in[0];
    const float* cw1 = (const float*)d_in[1];  const float* cb1 = (const float*)d_in[2];
    const float* cw2 = (const float*)d_in[3];  const float* cb2 = (const float*)d_in[4];
    const float* cw3 = (const float*)d_in[5];  const float* cb3 = (const float*)d_in[6];
    const float* cw4 = (const float*)d_in[7];  const float* cb4 = (const float*)d_in[8];
    const float* cw5 = (const float*)d_in[9];  const float* cb5 = (const float*)d_in[10];
    const float* w1  = (const float*)d_in[11]; const float* b1  = (const float*)d_in[12];
    const float* m1_vf = (const float*)d_in[13]; const float* m1_gf = (const float*)d_in[14];
    const float* m1_bf = (const float*)d_in[15]; const float* m1_vg = (const float*)d_in[16];
    const float* m1_gg = (const float*)d_in[17]; const float* m1_bg = (const float*)d_in[18];
    const float* w2  = (const float*)d_in[19]; const float* b2  = (const float*)d_in[20];
    const float* m2_vf = (const float*)d_in[21]; const float* m2_gf = (const float*)d_in[22];
    const float* m2_bf = (const float*)d_in[23]; const float* m2_vg = (const float*)d_in[24];
    const float* m2_gg = (const float*)d_in[25]; const float* m2_bg = (const float*)d_in[26];
    const float* w3  = (const float*)d_in[27]; const float* b3  = (const float*)d_in[28];
    float* out = (float*)d_out;

    __nv_bfloat16 *cat, *h2_bf, *wm1F, *wm1G, *wm2F, *wm2G, *w1g, *w2c;
    float *mid, *h2, *conv0, *conv1, *padb, *part, *feat, *bias1;
    cudaGetSymbolAddress((void**)&cat,   g_cat);
    cudaGetSymbolAddress((void**)&mid,   g_mid);
    cudaGetSymbolAddress((void**)&h2,    g_h2);
    cudaGetSymbolAddress((void**)&h2_bf, g_h2_bf);
    cudaGetSymbolAddress((void**)&wm1F,  g_wm1F);
    cudaGetSymbolAddress((void**)&wm1G,  g_wm1G);
    cudaGetSymbolAddress((void**)&wm2F,  g_wm2F);
    cudaGetSymbolAddress((void**)&wm2G,  g_wm2G);
    cudaGetSymbolAddress((void**)&w1g,   g_w1g_bf);
    cudaGetSymbolAddress((void**)&w2c,   g_w2cat);
    cudaGetSymbolAddress((void**)&conv0, g_conv0);
    cudaGetSymbolAddress((void**)&conv1, g_conv1);
    cudaGetSymbolAddress((void**)&padb,  g_pad);
    cudaGetSymbolAddress((void**)&part,  g_part);
    cudaGetSymbolAddress((void**)&feat,  g_feat);
    cudaGetSymbolAddress((void**)&bias1, g_bias1);

    // --- positional grid features into cat[:, 0:64] ---
    grid_kernel<<<(NPIX * 64) / 256, 256>>>(cat);

    // --- conv stack (pad + split across 4 ic-chunk blocks + reduce) ---
    launch_conv(feature, cw1, cb1, conv0, part, padb, 1792, 768, 8, 8, 8, 8, 1, 4);
    launch_conv(conv0,   cw2, cb2, conv1, part, padb, 768,  768, 8, 8, 8, 8, 1, 3);
    launch_conv(conv1,   cw3, cb3, conv0, part, padb, 768,  768, 8, 8, 8, 8, 1, 2);
    launch_conv(conv0,   cw4, cb4, conv1, part, padb, 768,  768, 8, 8, 6, 6, 0, 3);
    launch_conv(conv1,   cw5, cb5, feat,  part, padb, 768,  128, 6, 6, 4, 4, 0, 1);

    // --- fold feat @ w1[:,32:].T + b1 into a bias vector ---
    bias1_kernel<<<128, 256>>>(feat, w1, b1, bias1);

    // --- weight prep (bf16) ---
    wnorm_kernel<<<8 * 512, 128>>>(m1_vf, m1_gf, wm1F, 512);
    wnorm_kernel<<<8 * 512, 128>>>(m1_vg, m1_gg, wm1G, 512);
    wnorm_kernel<<<8 * 256, 128>>>(m2_vf, m2_gf, wm2F, 256);
    wnorm_kernel<<<8 * 256, 128>>>(m2_vg, m2_gg, wm2G, 256);
    conv_w1g_kernel<<<(1024 * 64) / 256, 256>>>(w1, w1g);
    conv_w2cat_kernel<<<(512 * 1088) / 256, 256>>>(w2, w2c);

    // --- mid = lrelu(grid @ w1grid.T + bias1): A = cat[:,0:64] ---
    launch_gemm(EP_LRELU_BIAS, cat, 1088, w1g, 64, mid, 1024, cat + 64, 1088,
                mid, 1024, bias1, NPIX, 1024, 64);

    // --- mem stack 1: halves of 1024 inside cat[:,64:1088] + fp32 mid ---
    for (int s = 0; s < 8; s++) {
        launch_gemm(EP_RES_OUT, cat + 64 + 512, 1088, wm1F + (size_t)s * 512 * 512, 512,
                    mid, 1024, cat + 64, 1088, mid, 1024, m1_bf + s * 512, NPIX, 512, 512);
        launch_gemm(EP_RES_OUT, cat + 64, 1088, wm1G + (size_t)s * 512 * 512, 512,
                    mid + 512, 1024, cat + 64 + 512, 1088, mid + 512, 1024, m1_bg + s * 512, NPIX, 512, 512);
    }

    // --- h2 = lrelu(cat @ w2cat.T + b2): single K=1088 GEMM ---
    launch_gemm(EP_LRELU_BIAS, cat, 1088, w2c, 1088, h2, 512, h2_bf, 512,
                h2, 512, b2, NPIX, 512, 1088);

    // --- mem stack 2: halves of 512 (256 each) ---
    for (int s = 0; s < 8; s++) {
        launch_gemm(EP_RES_OUT, h2_bf + 256, 512, wm2F + (size_t)s * 256 * 256, 256,
                    h2, 512, h2_bf, 512, h2, 512, m2_bf + s * 256, NPIX, 256, 256);
        launch_gemm(EP_RES_OUT, h2_bf, 512, wm2G + (size_t)s * 256 * 256, 256,
                    h2 + 256, 512, h2_bf + 256, 512, h2 + 256, 512, m2_bg + s * 256, NPIX, 256, 256);
    }

    // --- head (reads bf16 shadow) ---
    head_kernel<<<NPIX / 8, 256>>>(h2_bf, w3, b3, out);
}